// round 14
// baseline (speedup 1.0000x reference)
#include <cuda_runtime.h>
#include <cuda_fp16.h>
#include <stdint.h>
#include <math.h>

#define L_ 2048
#define B_ 16
#define D_ 512
#define H_ 1024
#define NC_ 16
#define NBASE 2176            // Z + H + 2D
#define MROWS (L_*B_)         // 32768
#define NCH 16                // EMA chunks
#define CHL 128               // chunk length

// ---------------- fp32 scratch ----------------
__device__ float g_base[MROWS*NBASE];  // activated base: [u | z | r | hx]
__device__ float g_o   [MROWS*D_];     // pre-norm output
__device__ float e_st  [4*NCH*8192];   // per-chunk local states
__device__ float seed_st[4*NCH*8192];  // per-chunk seeds

// ---------------- fp16 planes ----------------
__device__ __align__(16) __half xs_h [MROWS*D_];
__device__ __align__(16) __half mxs_h[MROWS*D_],  mxs_l[MROWS*D_];
__device__ __align__(16) __half hr_h [MROWS*H_];
__device__ __align__(16) __half vs_h [MROWS*H_];
__device__ __align__(16) __half wv_h [512*1024];
__device__ __align__(16) __half wmx_h[512*2176];
__device__ __align__(16) __half wh_h [1024*512];

__device__ __forceinline__ float sigmf(float x){ return 1.0f/(1.0f + expf(-x)); }
__device__ __forceinline__ float siluf(float x){ return x/(1.0f + expf(-x)); }
__device__ __forceinline__ void split2h(float v, __half& h, __half& l){
    h = __float2half_rn(v);
    l = __float2half_rn(v - __half2float(h));
}

#define MMA16816(d, a, b0, b1) \
  asm volatile("mma.sync.aligned.m16n8k16.row.col.f32.f16.f16.f32 " \
    "{%0,%1,%2,%3}, {%4,%5,%6,%7}, {%8,%9}, {%0,%1,%2,%3};" \
    : "+f"(d[0]), "+f"(d[1]), "+f"(d[2]), "+f"(d[3]) \
    : "r"(a[0]), "r"(a[1]), "r"(a[2]), "r"(a[3]), "r"(b0), "r"(b1))

#define LDSM4(r0,r1,r2,r3,a) \
  asm volatile("ldmatrix.sync.aligned.m8n8.x4.shared.b16 {%0,%1,%2,%3}, [%4];" \
    : "=r"(r0),"=r"(r1),"=r"(r2),"=r"(r3) : "r"(a))

#define LDSM4T(r0,r1,r2,r3,a) \
  asm volatile("ldmatrix.sync.aligned.m8n8.x4.trans.shared.b16 {%0,%1,%2,%3}, [%4];" \
    : "=r"(r0),"=r"(r1),"=r"(r2),"=r"(r3) : "r"(a))

#define CPA16(s,g) asm volatile("cp.async.cg.shared.global [%0], [%1], 16;" :: "r"(s), "l"(g))

// ---------------- all 3 weights: fp32 -> fp16, one launch ----------------
__global__ void __launch_bounds__(256) splitw_all(
    const float* __restrict__ Wv, const float* __restrict__ Wmx,
    const float* __restrict__ Wh)
{
    int bx = blockIdx.x;
    const float* src; __half* dst; int off;
    if (bx < 512)       { src = Wv;  dst = wv_h;  off = bx; }
    else if (bx < 1600) { src = Wmx; dst = wmx_h; off = bx - 512; }
    else                { src = Wh;  dst = wh_h;  off = bx - 1600; }
    size_t i4 = (size_t)off*256 + threadIdx.x;
    float4 v = *(const float4*)&src[i4*4];
    size_t o = i4*4;
    dst[o+0] = __float2half_rn(v.x);
    dst[o+1] = __float2half_rn(v.y);
    dst[o+2] = __float2half_rn(v.z);
    dst[o+3] = __float2half_rn(v.w);
}

// ---------------- EMA phase 1 ----------------
__global__ void __launch_bounds__(256) ema_p1(
    const float* __restrict__ x, const float* __restrict__ dlt,
    const float* __restrict__ alp)
{
    int t = blockIdx.x*256 + threadIdx.x;
    int c = t >> 13, bd = t & 8191;
    int d = bd & 511;
    int i0f = d*2, i1f = d*2 + 1;
    int i0b = (512 + d)*2, i1b = i0b + 1;
    float q0f = 1.f - sigmf(dlt[i0f])*sigmf(alp[i0f]);
    float q1f = 1.f - sigmf(dlt[i1f])*sigmf(alp[i1f]);
    float q0b = 1.f - sigmf(dlt[i0b])*sigmf(alp[i0b]);
    float q1b = 1.f - sigmf(dlt[i1b])*sigmf(alp[i1b]);

    float f0 = 0.f, f1 = 0.f, a0 = 0.f, a1 = 0.f, pw0 = 1.f, pw1 = 1.f;
    size_t idx = (size_t)(c*CHL)*8192 + bd;
    #pragma unroll 4
    for (int j = 0; j < CHL; j++, idx += 8192) {
        float xv = x[idx];
        f0 = fmaf(q0f, f0, xv);
        f1 = fmaf(q1f, f1, xv);
        a0 = fmaf(pw0, xv, a0);
        a1 = fmaf(pw1, xv, a1);
        pw0 *= q0b; pw1 *= q1b;
        xs_h[idx] = __float2half_rn(xv);
    }
    int o = c*8192 + bd;
    e_st[0*NCH*8192 + o] = f0;
    e_st[1*NCH*8192 + o] = f1;
    e_st[2*NCH*8192 + o] = a0;
    e_st[3*NCH*8192 + o] = a1;
}

// ---------------- EMA phase 2 ----------------
__global__ void __launch_bounds__(256) ema_p2(
    const float* __restrict__ dlt, const float* __restrict__ alp)
{
    int bd = blockIdx.x*256 + threadIdx.x;
    int d = bd & 511;
    int i0f = d*2, i1f = d*2 + 1;
    int i0b = (512 + d)*2, i1b = i0b + 1;
    float q0f = 1.f - sigmf(dlt[i0f])*sigmf(alp[i0f]);
    float q1f = 1.f - sigmf(dlt[i1f])*sigmf(alp[i1f]);
    float q0b = 1.f - sigmf(dlt[i0b])*sigmf(alp[i0b]);
    float q1b = 1.f - sigmf(dlt[i1b])*sigmf(alp[i1b]);
    float q0f8 = q0f, q1f8 = q1f, q0b8 = q0b, q1b8 = q1b;
    #pragma unroll
    for (int i = 0; i < 7; i++) { q0f8 *= q0f8; q1f8 *= q1f8; q0b8 *= q0b8; q1b8 *= q1b8; }

    float P0 = 0.f, P1 = 0.f;
    #pragma unroll
    for (int c = 0; c < NCH; c++) {
        int o = c*8192 + bd;
        seed_st[0*NCH*8192 + o] = P0;
        seed_st[1*NCH*8192 + o] = P1;
        P0 = fmaf(q0f8, P0, e_st[0*NCH*8192 + o]);
        P1 = fmaf(q1f8, P1, e_st[1*NCH*8192 + o]);
    }
    float T0 = 0.f, T1 = 0.f;
    #pragma unroll
    for (int c = NCH-1; c >= 0; c--) {
        int o = c*8192 + bd;
        seed_st[2*NCH*8192 + o] = T0;
        seed_st[3*NCH*8192 + o] = T1;
        T0 = fmaf(q0b8, T0, e_st[2*NCH*8192 + o]);
        T1 = fmaf(q1b8, T1, e_st[3*NCH*8192 + o]);
    }
}

// ---------------- EMA phase 3 ----------------
__global__ void __launch_bounds__(128) ema_p3(
    const float* __restrict__ x, const float* __restrict__ dlt,
    const float* __restrict__ alp, const float* __restrict__ bet,
    const float* __restrict__ gam, const float* __restrict__ omg)
{
    extern __shared__ float ybuf[];            // [CHL][128]
    int t = blockIdx.x*128 + threadIdx.x;
    int tid = threadIdx.x;
    int c = t >> 13, bd = t & 8191;
    int d = bd & 511;
    const float invs = 0.7071067811865476f;

    int i0f = d*2, i1f = d*2 + 1;
    int i0b = (512 + d)*2, i1b = i0b + 1;
    float p0f = sigmf(dlt[i0f]), p1f = sigmf(dlt[i1f]);
    float p0b = sigmf(dlt[i0b]), p1b = sigmf(dlt[i1b]);
    float q0f = 1.f - p0f*sigmf(alp[i0f]);
    float q1f = 1.f - p1f*sigmf(alp[i1f]);
    float q0b = 1.f - p0b*sigmf(alp[i0b]);
    float q1b = 1.f - p1b*sigmf(alp[i1b]);
    float w0f = p0f*bet[i0f]*gam[i0f]*invs;
    float w1f = p1f*bet[i1f]*gam[i1f]*invs;
    float w0b = p0b*bet[i0b]*gam[i0b]*invs;
    float w1b = p1b*bet[i1b]*gam[i1b]*invs;
    float ow = omg[d];

    int o = c*8192 + bd;
    size_t base = (size_t)(c*CHL)*8192 + bd;

    {
        float g0 = seed_st[2*NCH*8192 + o];
        float g1 = seed_st[3*NCH*8192 + o];
        size_t idx = base + (size_t)(CHL-1)*8192;
        #pragma unroll 4
        for (int j = CHL-1; j >= 0; j--, idx -= 8192) {
            float xv = x[idx];
            g0 = fmaf(q0b, g0, xv);
            g1 = fmaf(q1b, g1, xv);
            ybuf[j*128 + tid] = fmaf(w0b, g0, w1b*g1);
        }
    }
    {
        float f0 = seed_st[0*NCH*8192 + o];
        float f1 = seed_st[1*NCH*8192 + o];
        size_t idx = base;
        #pragma unroll 4
        for (int j = 0; j < CHL; j++, idx += 8192) {
            float xv = x[idx];
            f0 = fmaf(q0f, f0, xv);
            f1 = fmaf(q1f, f1, xv);
            float y = ybuf[j*128 + tid] + fmaf(w0f, f0, fmaf(w1f, f1, xv*ow));
            split2h(siluf(y), mxs_h[idx], mxs_l[idx]);
        }
    }
}

// ---------------- pipelined fp16 tensor-core GEMM (K-chunk 64) ----------------
// MODE 0: vs_h  = fp16(silu(xs @ Wv + bv))         N=1024 K=512
// MODE 1: g_base= act(mxs @ Wmx + bmx)             (u/r/hx merged 1-pass, z 2-pass)
// MODE 2: g_o   = gate(silu(hr @ Wh + bh + hx))    N=512  K=1024
template<int MODE, bool AS, int NOFF, bool M1MAP>
__global__ void __launch_bounds__(256, 2) mma_gemm(
    const float* __restrict__ Xres, const float* __restrict__ bias)
{
    constexpr int K   = (MODE==2) ? 1024 : 512;
    constexpr int ldA = (MODE==2) ? 1024 : 512;
    constexpr int ldB = (MODE==0) ? 1024 : (MODE==1) ? 2176 : 512;
    constexpr int NK  = K/64;
    constexpr int APS = 128*128;              // 16384: A plane (128 rows x 128B)
    constexpr int BOFF = (AS ? 2 : 1)*APS;
    constexpr int STAGE = BOFF + 16384;       // + B tile 64x256B
    constexpr int NST = AS ? 2 : 3;
    constexpr int NAE = AS ? 8 : 4;

    extern __shared__ __align__(128) char smem_raw[];
    const uint32_t sb = (uint32_t)__cvta_generic_to_shared(smem_raw);

    const int t = threadIdx.x;
    const int warp = t >> 5, lane = t & 31;
    const int wm = warp & 1, wn = warp >> 1;        // 2m x 4n
    const int group = lane >> 2, tid4 = lane & 3;
    const int mat = lane >> 3, rim = lane & 7;
    const int rOff = ((mat & 1) << 3) + rim;
    const int cOff = mat >> 1;

    int bn;
    if (M1MAP) bn = (blockIdx.x < 4) ? blockIdx.x*128 : 640 + (blockIdx.x - 4)*128;
    else       bn = NOFF + blockIdx.x * 128;
    const int bm = blockIdx.y * 128;

    const __half *pA0, *pA1 = nullptr, *pB0;
    if (MODE == 0) { pA0 = xs_h  + (size_t)bm*ldA;
                     pB0 = wv_h  + bn; }
    else if (MODE == 1) { pA0 = mxs_h + (size_t)bm*ldA; pA1 = mxs_l + (size_t)bm*ldA;
                          pB0 = wmx_h + bn; }
    else { pA0 = hr_h + (size_t)bm*ldA;
           pB0 = wh_h + bn; }

    const __half* gA[NAE]; uint32_t sA[NAE];
    #pragma unroll
    for (int e = 0; e < NAE; e++) {
        int idx = e*256 + t;
        int plane = idx >> 10, w = idx & 1023;
        int r = w >> 3, c = w & 7;
        gA[e] = (plane ? pA1 : pA0) + (size_t)r*ldA + c*8;
        sA[e] = sb + plane*APS + r*128 + (((uint32_t)(c ^ (r & 7))) << 4);
    }
    const __half* gB[4]; uint32_t sB[4];
    #pragma unroll
    for (int e = 0; e < 4; e++) {
        int idx = e*256 + t;
        int r = idx >> 4, c = idx & 15;
        gB[e] = pB0 + (size_t)r*ldB + c*8;
        sB[e] = sb + BOFF + r*256 + (((uint32_t)(c ^ (r & 7))) << 4);
    }

    auto load_chunk = [&](int ck) {
        uint32_t so = (uint32_t)(ck % NST) * STAGE;
        int ka = ck * 64;
        #pragma unroll
        for (int e = 0; e < NAE; e++) CPA16(sA[e] + so, gA[e] + ka);
        #pragma unroll
        for (int e = 0; e < 4; e++) CPA16(sB[e] + so, gB[e] + (size_t)ka*ldB);
        asm volatile("cp.async.commit_group;");
    };

    float acc[4][4][4];
    #pragma unroll
    for (int a = 0; a < 4; a++)
        #pragma unroll
        for (int b2 = 0; b2 < 4; b2++)
            #pragma unroll
            for (int e = 0; e < 4; e++) acc[a][b2][e] = 0.f;

    load_chunk(0);
    load_chunk(1);

    for (int it = 0; it < NK; it++) {
        if (it + 1 < NK) asm volatile("cp.async.wait_group 1;" ::: "memory");
        else             asm volatile("cp.async.wait_group 0;" ::: "memory");
        __syncthreads();
        if (NST == 3 && it + 2 < NK) load_chunk(it + 2);

        const uint32_t stg = sb + (uint32_t)(it % NST)*STAGE;
        #pragma unroll
        for (int ks = 0; ks < 4; ks++) {
            uint32_t bh[2][4];
            const int kin = ks*16 + rOff;
            #pragma unroll
            for (int g = 0; g < 2; g++) {
                int cB = wn*4 + g*2 + cOff;
                uint32_t bd = stg + BOFF + kin*256 + (((uint32_t)(cB ^ (kin & 7))) << 4);
                LDSM4T(bh[g][0], bh[g][1], bh[g][2], bh[g][3], bd);
            }
            #pragma unroll
            for (int mp = 0; mp < 2; mp++) {
                uint32_t ah[2][4], al[2][4];
                #pragma unroll
                for (int ml = 0; ml < 2; ml++) {
                    int row = wm*64 + (mp*2 + ml)*16 + rOff;
                    int cA = ks*2 + cOff;
                    uint32_t ad = stg + row*128 + (((uint32_t)(cA ^ (row & 7))) << 4);
                    LDSM4(ah[ml][0], ah[ml][1], ah[ml][2], ah[ml][3], ad);
                    if (AS) LDSM4(al[ml][0], al[ml][1], al[ml][2], al[ml][3], ad + APS);
                }
                #pragma unroll
                for (int g = 0; g < 2; g++) {
                    #pragma unroll
                    for (int ml = 0; ml < 2; ml++) {
                        int mt = mp*2 + ml;
                        MMA16816(acc[mt][g*2],   ah[ml], bh[g][0], bh[g][1]);
                        MMA16816(acc[mt][g*2+1], ah[ml], bh[g][2], bh[g][3]);
                        if (AS) {
                            MMA16816(acc[mt][g*2],   al[ml], bh[g][0], bh[g][1]);
                            MMA16816(acc[mt][g*2+1], al[ml], bh[g][2], bh[g][3]);
                        }
                    }
                }
            }
        }
        if (NST == 2) {
            __syncthreads();
            if (it + 2 < NK) load_chunk(it + 2);
        }
    }

    // ---- epilogue ----
    #pragma unroll
    for (int mt = 0; mt < 4; mt++) {
        #pragma unroll
        for (int nt = 0; nt < 4; nt++) {
            #pragma unroll
            for (int half = 0; half < 2; half++) {
                int m = bm + wm*64 + mt*16 + group + half*8;
                #pragma unroll
                for (int e = 0; e < 2; e++) {
                    int n = bn + wn*32 + nt*8 + tid4*2 + e;
                    float v = acc[mt][nt][half*2 + e];
                    if (MODE == 0) {
                        float s = siluf(v + bias[n]);
                        vs_h[(size_t)m*H_ + n] = __float2half_rn(s);
                    } else if (MODE == 1) {
                        v += bias[n];
                        if (n < 512)       v = sigmf(v);
                        else if (n < 1664) v = siluf(v);
                        g_base[(size_t)m*NBASE + n] = v;
                    } else {
                        float hx = g_base[(size_t)m*NBASE + 1664 + n];
                        float s  = siluf(v + bias[n] + hx);
                        float u  = g_base[(size_t)m*NBASE + n];
                        float xr = Xres[(size_t)m*D_ + n];
                        g_o[(size_t)m*D_ + n] = xr + u*(s - xr);
                    }
                }
            }
        }
    }
}

// ---------------- fused attention: QK + softmax + AV + r-gate ----------------
// One block per (b, chunk). Phase 1: fp32 QK + softmax (as before), writes
// attn_out fp32 and fp16 probs into smem. Phase 2: AV via fp16 MMA streaming
// v in 8 H-chunks (3-slot cp.async ring), epilogue multiplies r -> hr_h.
__global__ void __launch_bounds__(256) attn_kernel(
    const float* __restrict__ qkg, const float* __restrict__ qkb,
    const float* __restrict__ rp, float* __restrict__ attn_out)
{
    extern __shared__ float sm[];
    float* qT = sm;                 // [z][i] floats, bytes 0..65536
    float* kT = sm + 16384;         // bytes 65536..131072
    float* sT = sm + 32768;         // [j][i] stride 132, bytes 131072..198656
    float* red = sm + 8192;         // bytes 32768..35328 (beyond probs region)
    const uint32_t sb = (uint32_t)__cvta_generic_to_shared(sm);
    // probs fp16 [i][j] swizzled: bytes 0..32768 (reuses dead qT region)
    // B ring slots s=0..2: bytes 65536 + s*32768 (reuses kT then sT regions)

    const int b = blockIdx.x >> 4;
    const int c = blockIdx.x & 15;
    const int t = threadIdx.x;
    const int warp = t >> 5, lane = t & 31;
    const float qscale = 0.08838834764831845f;

    for (int idx = t; idx < 16384; idx += 256) {
        int i = idx >> 7, z = idx & 127;
        int row = (c*128 + i)*B_ + b;
        float zv = g_base[(size_t)row*NBASE + 512 + z];
        qT[z*128 + i] = (zv*qkg[z]     + qkb[z]    ) * qscale;
        kT[z*128 + i] =  zv*qkg[128+z] + qkb[128+z];
    }
    __syncthreads();

    {
        const int tx = t & 15, ty = t >> 4;
        const int i0 = ty*8, j0 = tx*8;
        float acc[8][8];
        #pragma unroll
        for (int i = 0; i < 8; i++)
            #pragma unroll
            for (int j = 0; j < 8; j++) acc[i][j] = 0.f;

        #pragma unroll 4
        for (int z = 0; z < 128; z++) {
            float qa[8], ka[8];
            *(float4*)(qa)   = *(const float4*)&qT[z*128 + i0];
            *(float4*)(qa+4) = *(const float4*)&qT[z*128 + i0 + 4];
            *(float4*)(ka)   = *(const float4*)&kT[z*128 + j0];
            *(float4*)(ka+4) = *(const float4*)&kT[z*128 + j0 + 4];
            #pragma unroll
            for (int i = 0; i < 8; i++)
                #pragma unroll
                for (int j = 0; j < 8; j++)
                    acc[i][j] = fmaf(qa[i], ka[j], acc[i][j]);
        }
        #pragma unroll
        for (int r = 0; r < 8; r++)
            #pragma unroll
            for (int cc2 = 0; cc2 < 8; cc2++) {
                int i = i0 + r, j = j0 + cc2;
                sT[j*132 + i] = acc[r][cc2] + rp[1023 + j - i];
            }
    }
    __syncthreads();
    // kT region now dead: prefetch v chunks 0 and 1 (overlaps softmax)
    auto issueB = [&](int hc) {
        uint32_t dstB = sb + 65536 + (uint32_t)(hc % 3)*32768;
        #pragma unroll
        for (int e = 0; e < 8; e++) {
            int idx = e*256 + t;            // 0..2047
            int j = idx >> 4, cu = idx & 15;
            const __half* src = vs_h + (size_t)((c*128 + j)*B_ + b)*H_ + hc*128 + cu*8;
            CPA16(dstB + j*256 + (((uint32_t)(cu ^ (j & 7))) << 4), src);
        }
        asm volatile("cp.async.commit_group;");
    };
    issueB(0);
    issueB(1);

    // softmax (2 threads per row)
    {
        const int i = t & 127, half = t >> 7;
        const int jb = half*64;
        float mx = -1e30f;
        for (int j = jb; j < jb + 64; j++) mx = fmaxf(mx, sT[j*132 + i]);
        red[half*128 + i] = mx;
        __syncthreads();
        float M = fmaxf(red[i], red[128 + i]);
        float s = 0.f;
        for (int j = jb; j < jb + 64; j++) {
            float e = expf(sT[j*132 + i] - M);
            sT[j*132 + i] = e;
            s += e;
        }
        red[256 + half*128 + i] = s;
        __syncthreads();
        if (half == 0) red[512 + i] = 1.f / (red[256 + i] + red[384 + i]);
        __syncthreads();
    }

    // attn_out fp32 (coalesced) + probs fp16 smem (swizzled)
    size_t obase = (size_t)(b*NC_ + c)*16384;
    float* aout = attn_out + obase;
    {
        const int i = t & 127;
        const int j8b = t >> 7;             // 0 or 1
        #pragma unroll
        for (int e = 0; e < 8; e++) {
            int j8 = j8b + e*2;             // 0..15
            float inv = red[512 + i];
            __half hv[8];
            #pragma unroll
            for (int w = 0; w < 8; w++) {
                int j = j8*8 + w;
                float p = sT[j*132 + i] * inv;
                aout[(size_t)i*128 + j] = p;
                hv[w] = __float2half_rn(p);
            }
            *(uint4*)((char*)sm + i*256 + (((uint32_t)(j8 ^ (i & 7))) << 4)) = *(uint4*)hv;
        }
    }
    __syncthreads();

    // ---- phase 2: AV MMA over 8 H-chunks ----
    const int wm = warp & 1, wn = warp >> 1;
    const int group = lane >> 2, tid4 = lane & 3;
    const int mat = lane >> 3, rim = lane & 7;
    const int rOff = ((mat & 1) << 3) + rim;
    const int cOff = mat >> 1;

    for (int hc = 0; hc < 8; hc++) {
        if (hc + 1 < 8) asm volatile("cp.async.wait_group 1;" ::: "memory");
        else            asm volatile("cp.async.wait_group 0;" ::: "memory");
        __syncthreads();
        if (hc + 2 < 8) issueB(hc + 2);

        const uint32_t Bb = sb + 65536 + (uint32_t)(hc % 3)*32768;
        float acc[4][4][4];
        #pragma unroll
        for (int a = 0; a < 4; a++)
            #pragma unroll
            for (int b2 = 0; b2 < 4; b2++)
                #pragma unroll
                for (int e = 0; e < 4; e++) acc[a][b2][e] = 0.f;

        #pragma unroll
        for (int ks = 0; ks < 8; ks++) {
            uint32_t bh[2][4];
            const int kin = ks*16 + rOff;
            #pragma unroll
            for (int g = 0; g < 2; g++) {
                int cB = wn*4 + g*2 + cOff;
                uint32_t bd = Bb + kin*256 + (((uint32_t)(cB ^ (kin & 7))) << 4);
                LDSM4T(bh[g][0], bh[g][1], bh[g][2], bh[g][3], bd);
            }
            #pragma unroll
            for (int mp = 0; mp < 2; mp++) {
                uint32_t ah[2][4];
                #pragma unroll
                for (int ml = 0; ml < 2; ml++) {
                    int row = wm*64 + (mp*2 + ml)*16 + rOff;
                    int cA = ks*2 + cOff;
                    uint32_t ad = sb + row*256 + (((uint32_t)(cA ^ (row & 7))) << 4);
                    LDSM4(ah[ml][0], ah[ml][1], ah[ml][2], ah[ml][3], ad);
                }
                #pragma unroll
                for (int g = 0; g < 2; g++) {
                    #pragma unroll
                    for (int ml = 0; ml < 2; ml++) {
                        int mt = mp*2 + ml;
                        MMA16816(acc[mt][g*2],   ah[ml], bh[g][0], bh[g][1]);
                        MMA16816(acc[mt][g*2+1], ah[ml], bh[g][2], bh[g][3]);
                    }
                }
            }
        }

        // epilogue: r-gate + hr write for this H-chunk
        #pragma unroll
        for (int mt = 0; mt < 4; mt++) {
            #pragma unroll
            for (int nt = 0; nt < 4; nt++) {
                #pragma unroll
                for (int half = 0; half < 2; half++) {
                    int m = wm*64 + mt*16 + group + half*8;
                    size_t row = (size_t)(c*128 + m)*B_ + b;
                    #pragma unroll
                    for (int e = 0; e < 2; e++) {
                        int n = hc*128 + wn*32 + nt*8 + tid4*2 + e;
                        float v = acc[mt][nt][half*2 + e];
                        float rv = g_base[row*NBASE + 640 + n];
                        hr_h[row*H_ + n] = __float2half_rn(v*rv);
                    }
                }
            }
        }
    }
}

// ---------------- final rmsnorm ----------------
__global__ void __launch_bounds__(256) norm_kernel(
    const float* __restrict__ ns, float* __restrict__ out)
{
    int row  = blockIdx.x*8 + (threadIdx.x >> 5);
    int lane = threadIdx.x & 31;
    const float* op = g_o + (size_t)row*512;
    float vals[16];
    float ss = 0.f;
    #pragma unroll
    for (int k = 0; k < 16; k++) {
        float v = op[lane + k*32];
        vals[k] = v;
        ss += v*v;
    }
    #pragma unroll
    for (int off = 16; off; off >>= 1) ss += __shfl_xor_sync(0xffffffffu, ss, off);
    float scale = ns[0] * rsqrtf(ss*(1.f/512.f) + 1e-6f);
    float* outp = out + (size_t)row*512;
    #pragma unroll
    for (int k = 0; k < 16; k++) outp[lane + k*32] = vals[k]*scale;
}

// ---------------- launch ----------------
extern "C" void kernel_launch(void* const* d_in, const int* in_sizes, int n_in,
                              void* d_out, int out_size)
{
    const float* x   = (const float*)d_in[0];
    const float* edl = (const float*)d_in[1];
    const float* eal = (const float*)d_in[2];
    const float* ebt = (const float*)d_in[3];
    const float* egm = (const float*)d_in[4];
    const float* eom = (const float*)d_in[5];
    const float* Wv  = (const float*)d_in[6];
    const float* bv  = (const float*)d_in[7];
    const float* Wmx = (const float*)d_in[8];
    const float* bmx = (const float*)d_in[9];
    const float* Wh  = (const float*)d_in[10];
    const float* bh  = (const float*)d_in[11];
    const float* qkg = (const float*)d_in[12];
    const float* qkb = (const float*)d_in[13];
    const float* rp  = (const float*)d_in[14];
    const float* ns  = (const float*)d_in[15];

    float* out      = (float*)d_out;
    float* attn_out = out + (size_t)L_*B_*D_;

    static bool init_done = false;
    if (!init_done) {
        cudaFuncSetAttribute(attn_kernel, cudaFuncAttributeMaxDynamicSharedMemorySize, 198656);
        cudaFuncSetAttribute(ema_p3,      cudaFuncAttributeMaxDynamicSharedMemorySize, 65536);
        cudaFuncSetAttribute((const void*)mma_gemm<0,false,0,false>,  cudaFuncAttributeMaxDynamicSharedMemorySize, 98304);
        cudaFuncSetAttribute((const void*)mma_gemm<1,false,0,true>,   cudaFuncAttributeMaxDynamicSharedMemorySize, 98304);
        cudaFuncSetAttribute((const void*)mma_gemm<1,true,512,false>, cudaFuncAttributeMaxDynamicSharedMemorySize, 98304);
        cudaFuncSetAttribute((const void*)mma_gemm<2,false,0,false>,  cudaFuncAttributeMaxDynamicSharedMemorySize, 98304);
        init_done = true;
    }

    splitw_all<<<2112, 256>>>(Wv, Wmx, Wh);

    ema_p1<<<512, 256>>>(x, edl, eal);
    ema_p2<<<32, 256>>>(edl, eal);
    ema_p3<<<1024, 128, 65536>>>(x, edl, eal, ebt, egm, eom);

    { dim3 g(8, 256);  mma_gemm<0,false,0,false><<<g, 256, 98304>>>(x, bv); }
    { dim3 g(16, 256); mma_gemm<1,false,0,true><<<g, 256, 98304>>>(x, bmx); }   // u + r + hx
    { dim3 g(1, 256);  mma_gemm<1,true,512,false><<<g, 256, 98304>>>(x, bmx); } // z (2-pass)

    attn_kernel<<<B_*NC_, 256, 198656>>>(qkg, qkb, rp, attn_out);

    { dim3 g(4, 256);  mma_gemm<2,false,0,false><<<g, 256, 98304>>>(x, bh); }

    norm_kernel<<<MROWS/8, 256>>>(ns, out);
}

// round 15
// speedup vs baseline: 1.1521x; 1.1521x over previous
#include <cuda_runtime.h>
#include <cuda_fp16.h>
#include <stdint.h>
#include <math.h>

#define L_ 2048
#define B_ 16
#define D_ 512
#define H_ 1024
#define NC_ 16
#define NBASE 2176            // Z + H + 2D
#define MROWS (L_*B_)         // 32768
#define NCH 32                // EMA chunks
#define CHL 64                // chunk length

// ---------------- fp32 scratch ----------------
__device__ float g_base[MROWS*NBASE];  // activated base: [u | z | r | hx]
__device__ float g_o   [MROWS*D_];     // pre-norm output
__device__ float e_st  [4*NCH*8192];   // per-chunk local states
__device__ float seed_st[4*NCH*8192];  // per-chunk seeds

// ---------------- fp16 planes ----------------
__device__ __align__(16) __half xs_h [MROWS*D_];
__device__ __align__(16) __half mxs_h[MROWS*D_],  mxs_l[MROWS*D_];
__device__ __align__(16) __half hr_h [MROWS*H_];
__device__ __align__(16) __half at_h [B_*NC_*128*128];
__device__ __align__(16) __half vs_h [MROWS*H_];
__device__ __align__(16) __half wv_h [512*1024];
__device__ __align__(16) __half wmx_h[512*2176];
__device__ __align__(16) __half wh_h [1024*512];

__device__ __forceinline__ float sigmf(float x){ return 1.0f/(1.0f + expf(-x)); }
__device__ __forceinline__ float siluf(float x){ return x/(1.0f + expf(-x)); }
__device__ __forceinline__ void split2h(float v, __half& h, __half& l){
    h = __float2half_rn(v);
    l = __float2half_rn(v - __half2float(h));
}

#define MMA16816(d, a, b0, b1) \
  asm volatile("mma.sync.aligned.m16n8k16.row.col.f32.f16.f16.f32 " \
    "{%0,%1,%2,%3}, {%4,%5,%6,%7}, {%8,%9}, {%0,%1,%2,%3};" \
    : "+f"(d[0]), "+f"(d[1]), "+f"(d[2]), "+f"(d[3]) \
    : "r"(a[0]), "r"(a[1]), "r"(a[2]), "r"(a[3]), "r"(b0), "r"(b1))

#define LDSM4(r0,r1,r2,r3,a) \
  asm volatile("ldmatrix.sync.aligned.m8n8.x4.shared.b16 {%0,%1,%2,%3}, [%4];" \
    : "=r"(r0),"=r"(r1),"=r"(r2),"=r"(r3) : "r"(a))

#define LDSM4T(r0,r1,r2,r3,a) \
  asm volatile("ldmatrix.sync.aligned.m8n8.x4.trans.shared.b16 {%0,%1,%2,%3}, [%4];" \
    : "=r"(r0),"=r"(r1),"=r"(r2),"=r"(r3) : "r"(a))

#define CPA16(s,g) asm volatile("cp.async.cg.shared.global [%0], [%1], 16;" :: "r"(s), "l"(g))

// ---------------- all 3 weights: fp32 -> fp16, one launch ----------------
__global__ void __launch_bounds__(256) splitw_all(
    const float* __restrict__ Wv, const float* __restrict__ Wmx,
    const float* __restrict__ Wh)
{
    int bx = blockIdx.x;
    const float* src; __half* dst; int off;
    if (bx < 512)       { src = Wv;  dst = wv_h;  off = bx; }
    else if (bx < 1600) { src = Wmx; dst = wmx_h; off = bx - 512; }
    else                { src = Wh;  dst = wh_h;  off = bx - 1600; }
    size_t i4 = (size_t)off*256 + threadIdx.x;
    float4 v = *(const float4*)&src[i4*4];
    size_t o = i4*4;
    dst[o+0] = __float2half_rn(v.x);
    dst[o+1] = __float2half_rn(v.y);
    dst[o+2] = __float2half_rn(v.z);
    dst[o+3] = __float2half_rn(v.w);
}

// ---------------- EMA phase 1: per-chunk local states + x->fp16 ----------------
__global__ void __launch_bounds__(256) ema_p1(
    const float* __restrict__ x, const float* __restrict__ dlt,
    const float* __restrict__ alp)
{
    int t = blockIdx.x*256 + threadIdx.x;      // 0..262143
    int c = t >> 13, bd = t & 8191;
    int d = bd & 511;
    int i0f = d*2, i1f = d*2 + 1;
    int i0b = (512 + d)*2, i1b = i0b + 1;
    float q0f = 1.f - sigmf(dlt[i0f])*sigmf(alp[i0f]);
    float q1f = 1.f - sigmf(dlt[i1f])*sigmf(alp[i1f]);
    float q0b = 1.f - sigmf(dlt[i0b])*sigmf(alp[i0b]);
    float q1b = 1.f - sigmf(dlt[i1b])*sigmf(alp[i1b]);

    float f0 = 0.f, f1 = 0.f, a0 = 0.f, a1 = 0.f, pw0 = 1.f, pw1 = 1.f;
    size_t idx = (size_t)(c*CHL)*8192 + bd;
    #pragma unroll 4
    for (int j = 0; j < CHL; j++, idx += 8192) {
        float xv = x[idx];
        f0 = fmaf(q0f, f0, xv);
        f1 = fmaf(q1f, f1, xv);
        a0 = fmaf(pw0, xv, a0);
        a1 = fmaf(pw1, xv, a1);
        pw0 *= q0b; pw1 *= q1b;
        xs_h[idx] = __float2half_rn(xv);
    }
    int o = c*8192 + bd;
    e_st[0*NCH*8192 + o] = f0;
    e_st[1*NCH*8192 + o] = f1;
    e_st[2*NCH*8192 + o] = a0;
    e_st[3*NCH*8192 + o] = a1;
}

// ---------------- EMA phase 2: cross-chunk prefix/suffix combine ----------------
__global__ void __launch_bounds__(256) ema_p2(
    const float* __restrict__ dlt, const float* __restrict__ alp)
{
    int bd = blockIdx.x*256 + threadIdx.x;
    int d = bd & 511;
    int i0f = d*2, i1f = d*2 + 1;
    int i0b = (512 + d)*2, i1b = i0b + 1;
    float q0f = 1.f - sigmf(dlt[i0f])*sigmf(alp[i0f]);
    float q1f = 1.f - sigmf(dlt[i1f])*sigmf(alp[i1f]);
    float q0b = 1.f - sigmf(dlt[i0b])*sigmf(alp[i0b]);
    float q1b = 1.f - sigmf(dlt[i1b])*sigmf(alp[i1b]);
    // q^64 via 6 squarings
    float q0f8 = q0f, q1f8 = q1f, q0b8 = q0b, q1b8 = q1b;
    #pragma unroll
    for (int i = 0; i < 6; i++) { q0f8 *= q0f8; q1f8 *= q1f8; q0b8 *= q0b8; q1b8 *= q1b8; }

    float P0 = 0.f, P1 = 0.f;
    #pragma unroll
    for (int c = 0; c < NCH; c++) {
        int o = c*8192 + bd;
        seed_st[0*NCH*8192 + o] = P0;
        seed_st[1*NCH*8192 + o] = P1;
        P0 = fmaf(q0f8, P0, e_st[0*NCH*8192 + o]);
        P1 = fmaf(q1f8, P1, e_st[1*NCH*8192 + o]);
    }
    float T0 = 0.f, T1 = 0.f;
    #pragma unroll
    for (int c = NCH-1; c >= 0; c--) {
        int o = c*8192 + bd;
        seed_st[2*NCH*8192 + o] = T0;
        seed_st[3*NCH*8192 + o] = T1;
        T0 = fmaf(q0b8, T0, e_st[2*NCH*8192 + o]);
        T1 = fmaf(q1b8, T1, e_st[3*NCH*8192 + o]);
    }
}

// ---------------- EMA phase 3: seeded scans + silu + split ----------------
__global__ void __launch_bounds__(128) ema_p3(
    const float* __restrict__ x, const float* __restrict__ dlt,
    const float* __restrict__ alp, const float* __restrict__ bet,
    const float* __restrict__ gam, const float* __restrict__ omg)
{
    extern __shared__ float ybuf[];            // [CHL][128] = 32KB
    int t = blockIdx.x*128 + threadIdx.x;      // 0..262143
    int tid = threadIdx.x;
    int c = t >> 13, bd = t & 8191;
    int d = bd & 511;
    const float invs = 0.7071067811865476f;

    int i0f = d*2, i1f = d*2 + 1;
    int i0b = (512 + d)*2, i1b = i0b + 1;
    float p0f = sigmf(dlt[i0f]), p1f = sigmf(dlt[i1f]);
    float p0b = sigmf(dlt[i0b]), p1b = sigmf(dlt[i1b]);
    float q0f = 1.f - p0f*sigmf(alp[i0f]);
    float q1f = 1.f - p1f*sigmf(alp[i1f]);
    float q0b = 1.f - p0b*sigmf(alp[i0b]);
    float q1b = 1.f - p1b*sigmf(alp[i1b]);
    float w0f = p0f*bet[i0f]*gam[i0f]*invs;
    float w1f = p1f*bet[i1f]*gam[i1f]*invs;
    float w0b = p0b*bet[i0b]*gam[i0b]*invs;
    float w1b = p1b*bet[i1b]*gam[i1b]*invs;
    float ow = omg[d];

    int o = c*8192 + bd;
    size_t base = (size_t)(c*CHL)*8192 + bd;

    {
        float g0 = seed_st[2*NCH*8192 + o];
        float g1 = seed_st[3*NCH*8192 + o];
        size_t idx = base + (size_t)(CHL-1)*8192;
        #pragma unroll 4
        for (int j = CHL-1; j >= 0; j--, idx -= 8192) {
            float xv = x[idx];
            g0 = fmaf(q0b, g0, xv);
            g1 = fmaf(q1b, g1, xv);
            ybuf[j*128 + tid] = fmaf(w0b, g0, w1b*g1);
        }
    }
    {
        float f0 = seed_st[0*NCH*8192 + o];
        float f1 = seed_st[1*NCH*8192 + o];
        size_t idx = base;
        #pragma unroll 4
        for (int j = 0; j < CHL; j++, idx += 8192) {
            float xv = x[idx];
            f0 = fmaf(q0f, f0, xv);
            f1 = fmaf(q1f, f1, xv);
            float y = ybuf[j*128 + tid] + fmaf(w0f, f0, fmaf(w1f, f1, xv*ow));
            split2h(siluf(y), mxs_h[idx], mxs_l[idx]);
        }
    }
}

// ---------------- pipelined fp16 tensor-core GEMM (K-chunk 64) ----------------
// MODE 0: vs_h  = fp16(silu(xs @ Wv + bv))         N=1024 K=512
// MODE 1: g_base= act(mxs @ Wmx + bmx)             (u/r/hx merged 1-pass, z 2-pass)
// MODE 2: g_o   = gate(silu(hr @ Wh + bh + hx))    N=512  K=1024
// MODE 3: hr_h  = fp16((attn @ v) * r)  (256 bat)  N=1024 K=128
template<int MODE, bool AS, int NOFF, bool M1MAP>
__global__ void __launch_bounds__(256, 2) mma_gemm(
    const float* __restrict__ Xres, const float* __restrict__ bias)
{
    constexpr int K   = (MODE==2) ? 1024 : (MODE==3) ? 128 : 512;
    constexpr int ldA = (MODE==2) ? 1024 : (MODE==3) ? 128 : 512;
    constexpr int ldB = (MODE==0) ? 1024 : (MODE==1) ? 2176 : (MODE==2) ? 512 : 16384;
    constexpr int NK  = K/64;
    constexpr int APS = 128*128;              // 16384: A plane (128 rows x 128B)
    constexpr int BOFF = (AS ? 2 : 1)*APS;
    constexpr int STAGE = BOFF + 16384;       // + B tile 64x256B
    constexpr int NST = AS ? 2 : 3;
    constexpr int NAE = AS ? 8 : 4;

    extern __shared__ __align__(128) char smem_raw[];
    const uint32_t sb = (uint32_t)__cvta_generic_to_shared(smem_raw);

    const int t = threadIdx.x;
    const int warp = t >> 5, lane = t & 31;
    const int wm = warp & 1, wn = warp >> 1;        // 2m x 4n
    const int group = lane >> 2, tid4 = lane & 3;
    const int mat = lane >> 3, rim = lane & 7;
    const int rOff = ((mat & 1) << 3) + rim;
    const int cOff = mat >> 1;

    int bn;
    if (M1MAP) bn = (blockIdx.x < 4) ? blockIdx.x*128 : 640 + (blockIdx.x - 4)*128;
    else       bn = NOFF + blockIdx.x * 128;
    const int bm = (MODE==3) ? 0 : blockIdx.y * 128;

    int bb = 0, cc = 0, batch = 0;
    if (MODE == 3) { batch = blockIdx.z; bb = batch >> 4; cc = batch & 15; }

    const __half *pA0, *pA1 = nullptr, *pB0;
    if (MODE == 0) { pA0 = xs_h  + (size_t)bm*ldA;
                     pB0 = wv_h  + bn; }
    else if (MODE == 1) { pA0 = mxs_h + (size_t)bm*ldA; pA1 = mxs_l + (size_t)bm*ldA;
                          pB0 = wmx_h + bn; }
    else if (MODE == 2) { pA0 = hr_h  + (size_t)bm*ldA;
                          pB0 = wh_h  + bn; }
    else { pA0 = at_h + (size_t)batch*16384;
           pB0 = vs_h + (size_t)(cc*2048 + bb)*H_ + bn; }

    const __half* gA[NAE]; uint32_t sA[NAE];
    #pragma unroll
    for (int e = 0; e < NAE; e++) {
        int idx = e*256 + t;
        int plane = idx >> 10, w = idx & 1023;
        int r = w >> 3, c = w & 7;
        gA[e] = (plane ? pA1 : pA0) + (size_t)r*ldA + c*8;
        sA[e] = sb + plane*APS + r*128 + (((uint32_t)(c ^ (r & 7))) << 4);
    }
    const __half* gB[4]; uint32_t sB[4];
    #pragma unroll
    for (int e = 0; e < 4; e++) {
        int idx = e*256 + t;
        int r = idx >> 4, c = idx & 15;
        gB[e] = pB0 + (size_t)r*ldB + c*8;
        sB[e] = sb + BOFF + r*256 + (((uint32_t)(c ^ (r & 7))) << 4);
    }

    auto load_chunk = [&](int ck) {
        uint32_t so = (uint32_t)(ck % NST) * STAGE;
        int ka = ck * 64;
        #pragma unroll
        for (int e = 0; e < NAE; e++) CPA16(sA[e] + so, gA[e] + ka);
        #pragma unroll
        for (int e = 0; e < 4; e++) CPA16(sB[e] + so, gB[e] + (size_t)ka*ldB);
        asm volatile("cp.async.commit_group;");
    };

    float acc[4][4][4];
    #pragma unroll
    for (int a = 0; a < 4; a++)
        #pragma unroll
        for (int b2 = 0; b2 < 4; b2++)
            #pragma unroll
            for (int e = 0; e < 4; e++) acc[a][b2][e] = 0.f;

    load_chunk(0);
    load_chunk(1);

    for (int it = 0; it < NK; it++) {
        if (it + 1 < NK) asm volatile("cp.async.wait_group 1;" ::: "memory");
        else             asm volatile("cp.async.wait_group 0;" ::: "memory");
        __syncthreads();
        if (NST == 3 && it + 2 < NK) load_chunk(it + 2);

        const uint32_t stg = sb + (uint32_t)(it % NST)*STAGE;
        #pragma unroll
        for (int ks = 0; ks < 4; ks++) {
            uint32_t bh[2][4];
            const int kin = ks*16 + rOff;
            #pragma unroll
            for (int g = 0; g < 2; g++) {
                int cB = wn*4 + g*2 + cOff;
                uint32_t bd = stg + BOFF + kin*256 + (((uint32_t)(cB ^ (kin & 7))) << 4);
                LDSM4T(bh[g][0], bh[g][1], bh[g][2], bh[g][3], bd);
            }
            #pragma unroll
            for (int mp = 0; mp < 2; mp++) {
                uint32_t ah[2][4], al[2][4];
                #pragma unroll
                for (int ml = 0; ml < 2; ml++) {
                    int row = wm*64 + (mp*2 + ml)*16 + rOff;
                    int cA = ks*2 + cOff;
                    uint32_t ad = stg + row*128 + (((uint32_t)(cA ^ (row & 7))) << 4);
                    LDSM4(ah[ml][0], ah[ml][1], ah[ml][2], ah[ml][3], ad);
                    if (AS) LDSM4(al[ml][0], al[ml][1], al[ml][2], al[ml][3], ad + APS);
                }
                #pragma unroll
                for (int g = 0; g < 2; g++) {
                    #pragma unroll
                    for (int ml = 0; ml < 2; ml++) {
                        int mt = mp*2 + ml;
                        MMA16816(acc[mt][g*2],   ah[ml], bh[g][0], bh[g][1]);
                        MMA16816(acc[mt][g*2+1], ah[ml], bh[g][2], bh[g][3]);
                        if (AS) {
                            MMA16816(acc[mt][g*2],   al[ml], bh[g][0], bh[g][1]);
                            MMA16816(acc[mt][g*2+1], al[ml], bh[g][2], bh[g][3]);
                        }
                    }
                }
            }
        }
        if (NST == 2) {
            __syncthreads();
            if (it + 2 < NK) load_chunk(it + 2);
        }
    }

    // ---- epilogue ----
    #pragma unroll
    for (int mt = 0; mt < 4; mt++) {
        #pragma unroll
        for (int nt = 0; nt < 4; nt++) {
            #pragma unroll
            for (int half = 0; half < 2; half++) {
                int m = bm + wm*64 + mt*16 + group + half*8;
                #pragma unroll
                for (int e = 0; e < 2; e++) {
                    int n = bn + wn*32 + nt*8 + tid4*2 + e;
                    float v = acc[mt][nt][half*2 + e];
                    if (MODE == 0) {
                        float s = siluf(v + bias[n]);
                        vs_h[(size_t)m*H_ + n] = __float2half_rn(s);
                    } else if (MODE == 1) {
                        v += bias[n];
                        if (n < 512)       v = sigmf(v);
                        else if (n < 1664) v = siluf(v);
                        g_base[(size_t)m*NBASE + n] = v;
                    } else if (MODE == 2) {
                        float hx = g_base[(size_t)m*NBASE + 1664 + n];
                        float s  = siluf(v + bias[n] + hx);
                        float u  = g_base[(size_t)m*NBASE + n];
                        float xr = Xres[(size_t)m*D_ + n];
                        g_o[(size_t)m*D_ + n] = xr + u*(s - xr);
                    } else {
                        size_t row = (size_t)(cc*128 + m)*B_ + bb;
                        float rv = g_base[row*NBASE + 640 + n];
                        hr_h[row*H_ + n] = __float2half_rn(v*rv);
                    }
                }
            }
        }
    }
}

// ---------------- QK + softmax ----------------
__global__ void __launch_bounds__(256) qk_kernel(
    const float* __restrict__ qkg, const float* __restrict__ qkb,
    const float* __restrict__ rp, float* __restrict__ attn_out)
{
    extern __shared__ float sm[];
    float* qT = sm;
    float* kT = sm + 16384;
    float* sT = sm + 32768;
    float* red = sm;

    const int b = blockIdx.x >> 4;
    const int c = blockIdx.x & 15;
    const int t = threadIdx.x;
    const float qscale = 0.08838834764831845f;

    for (int idx = t; idx < 16384; idx += 256) {
        int i = idx >> 7, z = idx & 127;
        int row = (c*128 + i)*B_ + b;
        float zv = g_base[(size_t)row*NBASE + 512 + z];
        qT[z*128 + i] = (zv*qkg[z]     + qkb[z]    ) * qscale;
        kT[z*128 + i] =  zv*qkg[128+z] + qkb[128+z];
    }
    __syncthreads();

    {
        const int tx = t & 15, ty = t >> 4;
        const int i0 = ty*8, j0 = tx*8;
        float acc[8][8];
        #pragma unroll
        for (int i = 0; i < 8; i++)
            #pragma unroll
            for (int j = 0; j < 8; j++) acc[i][j] = 0.f;

        #pragma unroll 4
        for (int z = 0; z < 128; z++) {
            float qa[8], ka[8];
            *(float4*)(qa)   = *(const float4*)&qT[z*128 + i0];
            *(float4*)(qa+4) = *(const float4*)&qT[z*128 + i0 + 4];
            *(float4*)(ka)   = *(const float4*)&kT[z*128 + j0];
            *(float4*)(ka+4) = *(const float4*)&kT[z*128 + j0 + 4];
            #pragma unroll
            for (int i = 0; i < 8; i++)
                #pragma unroll
                for (int j = 0; j < 8; j++)
                    acc[i][j] = fmaf(qa[i], ka[j], acc[i][j]);
        }
        #pragma unroll
        for (int r = 0; r < 8; r++)
            #pragma unroll
            for (int cc2 = 0; cc2 < 8; cc2++) {
                int i = i0 + r, j = j0 + cc2;
                sT[j*132 + i] = acc[r][cc2] + rp[1023 + j - i];
            }
    }
    __syncthreads();

    {
        const int i = t & 127, half = t >> 7;
        const int jb = half*64;
        float mx = -1e30f;
        for (int j = jb; j < jb + 64; j++) mx = fmaxf(mx, sT[j*132 + i]);
        red[half*128 + i] = mx;
        __syncthreads();
        float M = fmaxf(red[i], red[128 + i]);
        float s = 0.f;
        for (int j = jb; j < jb + 64; j++) {
            float e = expf(sT[j*132 + i] - M);
            sT[j*132 + i] = e;
            s += e;
        }
        red[256 + half*128 + i] = s;
        __syncthreads();
        if (half == 0) red[512 + i] = 1.f / (red[256 + i] + red[384 + i]);
        __syncthreads();
    }

    size_t base = (size_t)(b*NC_ + c)*16384;
    float* aout = attn_out + base;
    for (int idx = t; idx < 16384; idx += 256) {
        int i = idx >> 7, j = idx & 127;
        float p = sT[j*132 + i] * red[512 + i];
        aout[idx] = p;
        at_h[base + idx] = __float2half_rn(p);
    }
}

// ---------------- final rmsnorm ----------------
__global__ void __launch_bounds__(256) norm_kernel(
    const float* __restrict__ ns, float* __restrict__ out)
{
    int row  = blockIdx.x*8 + (threadIdx.x >> 5);
    int lane = threadIdx.x & 31;
    const float* op = g_o + (size_t)row*512;
    float vals[16];
    float ss = 0.f;
    #pragma unroll
    for (int k = 0; k < 16; k++) {
        float v = op[lane + k*32];
        vals[k] = v;
        ss += v*v;
    }
    #pragma unroll
    for (int off = 16; off; off >>= 1) ss += __shfl_xor_sync(0xffffffffu, ss, off);
    float scale = ns[0] * rsqrtf(ss*(1.f/512.f) + 1e-6f);
    float* outp = out + (size_t)row*512;
    #pragma unroll
    for (int k = 0; k < 16; k++) outp[lane + k*32] = vals[k]*scale;
}

// ---------------- launch ----------------
extern "C" void kernel_launch(void* const* d_in, const int* in_sizes, int n_in,
                              void* d_out, int out_size)
{
    const float* x   = (const float*)d_in[0];
    const float* edl = (const float*)d_in[1];
    const float* eal = (const float*)d_in[2];
    const float* ebt = (const float*)d_in[3];
    const float* egm = (const float*)d_in[4];
    const float* eom = (const float*)d_in[5];
    const float* Wv  = (const float*)d_in[6];
    const float* bv  = (const float*)d_in[7];
    const float* Wmx = (const float*)d_in[8];
    const float* bmx = (const float*)d_in[9];
    const float* Wh  = (const float*)d_in[10];
    const float* bh  = (const float*)d_in[11];
    const float* qkg = (const float*)d_in[12];
    const float* qkb = (const float*)d_in[13];
    const float* rp  = (const float*)d_in[14];
    const float* ns  = (const float*)d_in[15];

    float* out      = (float*)d_out;
    float* attn_out = out + (size_t)L_*B_*D_;

    static bool init_done = false;
    if (!init_done) {
        cudaFuncSetAttribute(qk_kernel, cudaFuncAttributeMaxDynamicSharedMemorySize, 198656);
        cudaFuncSetAttribute(ema_p3,    cudaFuncAttributeMaxDynamicSharedMemorySize, 32768);
        cudaFuncSetAttribute((const void*)mma_gemm<0,false,0,false>,  cudaFuncAttributeMaxDynamicSharedMemorySize, 98304);
        cudaFuncSetAttribute((const void*)mma_gemm<1,false,0,true>,   cudaFuncAttributeMaxDynamicSharedMemorySize, 98304);
        cudaFuncSetAttribute((const void*)mma_gemm<1,true,512,false>, cudaFuncAttributeMaxDynamicSharedMemorySize, 98304);
        cudaFuncSetAttribute((const void*)mma_gemm<2,false,0,false>,  cudaFuncAttributeMaxDynamicSharedMemorySize, 98304);
        cudaFuncSetAttribute((const void*)mma_gemm<3,false,0,false>,  cudaFuncAttributeMaxDynamicSharedMemorySize, 98304);
        init_done = true;
    }

    splitw_all<<<2112, 256>>>(Wv, Wmx, Wh);

    ema_p1<<<1024, 256>>>(x, edl, eal);
    ema_p2<<<32, 256>>>(edl, eal);
    ema_p3<<<2048, 128, 32768>>>(x, edl, eal, ebt, egm, eom);

    { dim3 g(8, 256);  mma_gemm<0,false,0,false><<<g, 256, 98304>>>(x, bv); }
    { dim3 g(16, 256); mma_gemm<1,false,0,true><<<g, 256, 98304>>>(x, bmx); }   // u + r + hx
    { dim3 g(1, 256);  mma_gemm<1,true,512,false><<<g, 256, 98304>>>(x, bmx); } // z (2-pass)

    qk_kernel<<<B_*NC_, 256, 198656>>>(qkg, qkb, rp, attn_out);

    { dim3 g(8, 1, 256); mma_gemm<3,false,0,false><<<g, 256, 98304>>>(x, bv); }
    { dim3 g(4, 256);    mma_gemm<2,false,0,false><<<g, 256, 98304>>>(x, bh); }

    norm_kernel<<<MROWS/8, 256>>>(ns, out);
}

// round 16
// speedup vs baseline: 1.1929x; 1.0354x over previous
#include <cuda_runtime.h>
#include <cuda_fp16.h>
#include <stdint.h>
#include <math.h>

#define L_ 2048
#define B_ 16
#define D_ 512
#define H_ 1024
#define NC_ 16
#define NBASE 2176            // Z + H + 2D
#define MROWS (L_*B_)         // 32768
#define NCH 64                // EMA chunks
#define CHL 32                // chunk length

// ---------------- fp32 scratch ----------------
__device__ float g_base[MROWS*NBASE];  // activated base: [u | z | r | hx]
__device__ float g_o   [MROWS*D_];     // pre-norm output
__device__ float e_st  [4*NCH*8192];   // per-chunk local states
__device__ float seed_st[4*NCH*8192];  // per-chunk seeds

// ---------------- fp16 planes ----------------
__device__ __align__(16) __half xs_h [MROWS*D_];
__device__ __align__(16) __half mxs_h[MROWS*D_],  mxs_l[MROWS*D_];
__device__ __align__(16) __half hr_h [MROWS*H_];
__device__ __align__(16) __half at_h [B_*NC_*128*128];
__device__ __align__(16) __half vs_h [MROWS*H_];
__device__ __align__(16) __half wv_h [512*1024];
__device__ __align__(16) __half wmx_h[512*2176];
__device__ __align__(16) __half wh_h [1024*512];

__device__ __forceinline__ float sigmf(float x){ return 1.0f/(1.0f + expf(-x)); }
__device__ __forceinline__ float siluf(float x){ return x/(1.0f + expf(-x)); }
__device__ __forceinline__ void split2h(float v, __half& h, __half& l){
    h = __float2half_rn(v);
    l = __float2half_rn(v - __half2float(h));
}

#define MMA16816(d, a, b0, b1) \
  asm volatile("mma.sync.aligned.m16n8k16.row.col.f32.f16.f16.f32 " \
    "{%0,%1,%2,%3}, {%4,%5,%6,%7}, {%8,%9}, {%0,%1,%2,%3};" \
    : "+f"(d[0]), "+f"(d[1]), "+f"(d[2]), "+f"(d[3]) \
    : "r"(a[0]), "r"(a[1]), "r"(a[2]), "r"(a[3]), "r"(b0), "r"(b1))

#define LDSM4(r0,r1,r2,r3,a) \
  asm volatile("ldmatrix.sync.aligned.m8n8.x4.shared.b16 {%0,%1,%2,%3}, [%4];" \
    : "=r"(r0),"=r"(r1),"=r"(r2),"=r"(r3) : "r"(a))

#define LDSM4T(r0,r1,r2,r3,a) \
  asm volatile("ldmatrix.sync.aligned.m8n8.x4.trans.shared.b16 {%0,%1,%2,%3}, [%4];" \
    : "=r"(r0),"=r"(r1),"=r"(r2),"=r"(r3) : "r"(a))

#define CPA16(s,g) asm volatile("cp.async.cg.shared.global [%0], [%1], 16;" :: "r"(s), "l"(g))

// ---------------- all 3 weights: fp32 -> fp16, one launch ----------------
__global__ void __launch_bounds__(256) splitw_all(
    const float* __restrict__ Wv, const float* __restrict__ Wmx,
    const float* __restrict__ Wh)
{
    int bx = blockIdx.x;
    const float* src; __half* dst; int off;
    if (bx < 512)       { src = Wv;  dst = wv_h;  off = bx; }
    else if (bx < 1600) { src = Wmx; dst = wmx_h; off = bx - 512; }
    else                { src = Wh;  dst = wh_h;  off = bx - 1600; }
    size_t i4 = (size_t)off*256 + threadIdx.x;
    float4 v = *(const float4*)&src[i4*4];
    size_t o = i4*4;
    dst[o+0] = __float2half_rn(v.x);
    dst[o+1] = __float2half_rn(v.y);
    dst[o+2] = __float2half_rn(v.z);
    dst[o+3] = __float2half_rn(v.w);
}

// ---------------- EMA phase 1: per-chunk local states + x->fp16 ----------------
__global__ void __launch_bounds__(256) ema_p1(
    const float* __restrict__ x, const float* __restrict__ dlt,
    const float* __restrict__ alp)
{
    int t = blockIdx.x*256 + threadIdx.x;      // 0..524287
    int c = t >> 13, bd = t & 8191;
    int d = bd & 511;
    int i0f = d*2, i1f = d*2 + 1;
    int i0b = (512 + d)*2, i1b = i0b + 1;
    float q0f = 1.f - sigmf(dlt[i0f])*sigmf(alp[i0f]);
    float q1f = 1.f - sigmf(dlt[i1f])*sigmf(alp[i1f]);
    float q0b = 1.f - sigmf(dlt[i0b])*sigmf(alp[i0b]);
    float q1b = 1.f - sigmf(dlt[i1b])*sigmf(alp[i1b]);

    float f0 = 0.f, f1 = 0.f, a0 = 0.f, a1 = 0.f, pw0 = 1.f, pw1 = 1.f;
    size_t idx = (size_t)(c*CHL)*8192 + bd;
    #pragma unroll 4
    for (int j = 0; j < CHL; j++, idx += 8192) {
        float xv = x[idx];
        f0 = fmaf(q0f, f0, xv);
        f1 = fmaf(q1f, f1, xv);
        a0 = fmaf(pw0, xv, a0);
        a1 = fmaf(pw1, xv, a1);
        pw0 *= q0b; pw1 *= q1b;
        xs_h[idx] = __float2half_rn(xv);
    }
    int o = c*8192 + bd;
    e_st[0*NCH*8192 + o] = f0;
    e_st[1*NCH*8192 + o] = f1;
    e_st[2*NCH*8192 + o] = a0;
    e_st[3*NCH*8192 + o] = a1;
}

// ---------------- EMA phase 2: cross-chunk prefix/suffix combine ----------------
__global__ void __launch_bounds__(256) ema_p2(
    const float* __restrict__ dlt, const float* __restrict__ alp)
{
    int bd = blockIdx.x*256 + threadIdx.x;
    int d = bd & 511;
    int i0f = d*2, i1f = d*2 + 1;
    int i0b = (512 + d)*2, i1b = i0b + 1;
    float q0f = 1.f - sigmf(dlt[i0f])*sigmf(alp[i0f]);
    float q1f = 1.f - sigmf(dlt[i1f])*sigmf(alp[i1f]);
    float q0b = 1.f - sigmf(dlt[i0b])*sigmf(alp[i0b]);
    float q1b = 1.f - sigmf(dlt[i1b])*sigmf(alp[i1b]);
    // q^32 via 5 squarings
    float q0f8 = q0f, q1f8 = q1f, q0b8 = q0b, q1b8 = q1b;
    #pragma unroll
    for (int i = 0; i < 5; i++) { q0f8 *= q0f8; q1f8 *= q1f8; q0b8 *= q0b8; q1b8 *= q1b8; }

    float P0 = 0.f, P1 = 0.f;
    #pragma unroll
    for (int c = 0; c < NCH; c++) {
        int o = c*8192 + bd;
        seed_st[0*NCH*8192 + o] = P0;
        seed_st[1*NCH*8192 + o] = P1;
        P0 = fmaf(q0f8, P0, e_st[0*NCH*8192 + o]);
        P1 = fmaf(q1f8, P1, e_st[1*NCH*8192 + o]);
    }
    float T0 = 0.f, T1 = 0.f;
    #pragma unroll
    for (int c = NCH-1; c >= 0; c--) {
        int o = c*8192 + bd;
        seed_st[2*NCH*8192 + o] = T0;
        seed_st[3*NCH*8192 + o] = T1;
        T0 = fmaf(q0b8, T0, e_st[2*NCH*8192 + o]);
        T1 = fmaf(q1b8, T1, e_st[3*NCH*8192 + o]);
    }
}

// ---------------- EMA phase 3: seeded scans + silu + split ----------------
__global__ void __launch_bounds__(128) ema_p3(
    const float* __restrict__ x, const float* __restrict__ dlt,
    const float* __restrict__ alp, const float* __restrict__ bet,
    const float* __restrict__ gam, const float* __restrict__ omg)
{
    extern __shared__ float ybuf[];            // [CHL][128] = 16KB
    int t = blockIdx.x*128 + threadIdx.x;      // 0..524287
    int tid = threadIdx.x;
    int c = t >> 13, bd = t & 8191;
    int d = bd & 511;
    const float invs = 0.7071067811865476f;

    int i0f = d*2, i1f = d*2 + 1;
    int i0b = (512 + d)*2, i1b = i0b + 1;
    float p0f = sigmf(dlt[i0f]), p1f = sigmf(dlt[i1f]);
    float p0b = sigmf(dlt[i0b]), p1b = sigmf(dlt[i1b]);
    float q0f = 1.f - p0f*sigmf(alp[i0f]);
    float q1f = 1.f - p1f*sigmf(alp[i1f]);
    float q0b = 1.f - p0b*sigmf(alp[i0b]);
    float q1b = 1.f - p1b*sigmf(alp[i1b]);
    float w0f = p0f*bet[i0f]*gam[i0f]*invs;
    float w1f = p1f*bet[i1f]*gam[i1f]*invs;
    float w0b = p0b*bet[i0b]*gam[i0b]*invs;
    float w1b = p1b*bet[i1b]*gam[i1b]*invs;
    float ow = omg[d];

    int o = c*8192 + bd;
    size_t base = (size_t)(c*CHL)*8192 + bd;

    {
        float g0 = seed_st[2*NCH*8192 + o];
        float g1 = seed_st[3*NCH*8192 + o];
        size_t idx = base + (size_t)(CHL-1)*8192;
        #pragma unroll 4
        for (int j = CHL-1; j >= 0; j--, idx -= 8192) {
            float xv = x[idx];
            g0 = fmaf(q0b, g0, xv);
            g1 = fmaf(q1b, g1, xv);
            ybuf[j*128 + tid] = fmaf(w0b, g0, w1b*g1);
        }
    }
    {
        float f0 = seed_st[0*NCH*8192 + o];
        float f1 = seed_st[1*NCH*8192 + o];
        size_t idx = base;
        #pragma unroll 4
        for (int j = 0; j < CHL; j++, idx += 8192) {
            float xv = x[idx];
            f0 = fmaf(q0f, f0, xv);
            f1 = fmaf(q1f, f1, xv);
            float y = ybuf[j*128 + tid] + fmaf(w0f, f0, fmaf(w1f, f1, xv*ow));
            split2h(siluf(y), mxs_h[idx], mxs_l[idx]);
        }
    }
}

// ---------------- pipelined fp16 tensor-core GEMM (K-chunk 64) ----------------
// MODE 0: vs_h  = fp16(silu(xs @ Wv + bv))         N=1024 K=512
// MODE 1: g_base= act(mxs @ Wmx + bmx)             (u/r/hx merged 1-pass, z 2-pass)
// MODE 2: g_o   = gate(silu(hr @ Wh + bh + hx))    N=512  K=1024
// MODE 3: hr_h  = fp16((attn @ v) * r)  (256 bat)  N=1024 K=128
template<int MODE, bool AS, int NOFF, bool M1MAP>
__global__ void __launch_bounds__(256, 2) mma_gemm(
    const float* __restrict__ Xres, const float* __restrict__ bias)
{
    constexpr int K   = (MODE==2) ? 1024 : (MODE==3) ? 128 : 512;
    constexpr int ldA = (MODE==2) ? 1024 : (MODE==3) ? 128 : 512;
    constexpr int ldB = (MODE==0) ? 1024 : (MODE==1) ? 2176 : (MODE==2) ? 512 : 16384;
    constexpr int NK  = K/64;
    constexpr int APS = 128*128;              // 16384: A plane (128 rows x 128B)
    constexpr int BOFF = (AS ? 2 : 1)*APS;
    constexpr int STAGE = BOFF + 16384;       // + B tile 64x256B
    constexpr int NST = AS ? 2 : 3;
    constexpr int NAE = AS ? 8 : 4;

    extern __shared__ __align__(128) char smem_raw[];
    const uint32_t sb = (uint32_t)__cvta_generic_to_shared(smem_raw);

    const int t = threadIdx.x;
    const int warp = t >> 5, lane = t & 31;
    const int wm = warp & 1, wn = warp >> 1;        // 2m x 4n
    const int group = lane >> 2, tid4 = lane & 3;
    const int mat = lane >> 3, rim = lane & 7;
    const int rOff = ((mat & 1) << 3) + rim;
    const int cOff = mat >> 1;

    int bn;
    if (M1MAP) bn = (blockIdx.x < 4) ? blockIdx.x*128 : 640 + (blockIdx.x - 4)*128;
    else       bn = NOFF + blockIdx.x * 128;
    const int bm = (MODE==3) ? 0 : blockIdx.y * 128;

    int bb = 0, cc = 0, batch = 0;
    if (MODE == 3) { batch = blockIdx.z; bb = batch >> 4; cc = batch & 15; }

    const __half *pA0, *pA1 = nullptr, *pB0;
    if (MODE == 0) { pA0 = xs_h  + (size_t)bm*ldA;
                     pB0 = wv_h  + bn; }
    else if (MODE == 1) { pA0 = mxs_h + (size_t)bm*ldA; pA1 = mxs_l + (size_t)bm*ldA;
                          pB0 = wmx_h + bn; }
    else if (MODE == 2) { pA0 = hr_h  + (size_t)bm*ldA;
                          pB0 = wh_h  + bn; }
    else { pA0 = at_h + (size_t)batch*16384;
           pB0 = vs_h + (size_t)(cc*2048 + bb)*H_ + bn; }

    const __half* gA[NAE]; uint32_t sA[NAE];
    #pragma unroll
    for (int e = 0; e < NAE; e++) {
        int idx = e*256 + t;
        int plane = idx >> 10, w = idx & 1023;
        int r = w >> 3, c = w & 7;
        gA[e] = (plane ? pA1 : pA0) + (size_t)r*ldA + c*8;
        sA[e] = sb + plane*APS + r*128 + (((uint32_t)(c ^ (r & 7))) << 4);
    }
    const __half* gB[4]; uint32_t sB[4];
    #pragma unroll
    for (int e = 0; e < 4; e++) {
        int idx = e*256 + t;
        int r = idx >> 4, c = idx & 15;
        gB[e] = pB0 + (size_t)r*ldB + c*8;
        sB[e] = sb + BOFF + r*256 + (((uint32_t)(c ^ (r & 7))) << 4);
    }

    auto load_chunk = [&](int ck) {
        uint32_t so = (uint32_t)(ck % NST) * STAGE;
        int ka = ck * 64;
        #pragma unroll
        for (int e = 0; e < NAE; e++) CPA16(sA[e] + so, gA[e] + ka);
        #pragma unroll
        for (int e = 0; e < 4; e++) CPA16(sB[e] + so, gB[e] + (size_t)ka*ldB);
        asm volatile("cp.async.commit_group;");
    };

    float acc[4][4][4];
    #pragma unroll
    for (int a = 0; a < 4; a++)
        #pragma unroll
        for (int b2 = 0; b2 < 4; b2++)
            #pragma unroll
            for (int e = 0; e < 4; e++) acc[a][b2][e] = 0.f;

    load_chunk(0);
    load_chunk(1);

    for (int it = 0; it < NK; it++) {
        if (it + 1 < NK) asm volatile("cp.async.wait_group 1;" ::: "memory");
        else             asm volatile("cp.async.wait_group 0;" ::: "memory");
        __syncthreads();
        if (NST == 3 && it + 2 < NK) load_chunk(it + 2);

        const uint32_t stg = sb + (uint32_t)(it % NST)*STAGE;
        #pragma unroll
        for (int ks = 0; ks < 4; ks++) {
            uint32_t bh[2][4];
            const int kin = ks*16 + rOff;
            #pragma unroll
            for (int g = 0; g < 2; g++) {
                int cB = wn*4 + g*2 + cOff;
                uint32_t bd = stg + BOFF + kin*256 + (((uint32_t)(cB ^ (kin & 7))) << 4);
                LDSM4T(bh[g][0], bh[g][1], bh[g][2], bh[g][3], bd);
            }
            #pragma unroll
            for (int mp = 0; mp < 2; mp++) {
                uint32_t ah[2][4], al[2][4];
                #pragma unroll
                for (int ml = 0; ml < 2; ml++) {
                    int row = wm*64 + (mp*2 + ml)*16 + rOff;
                    int cA = ks*2 + cOff;
                    uint32_t ad = stg + row*128 + (((uint32_t)(cA ^ (row & 7))) << 4);
                    LDSM4(ah[ml][0], ah[ml][1], ah[ml][2], ah[ml][3], ad);
                    if (AS) LDSM4(al[ml][0], al[ml][1], al[ml][2], al[ml][3], ad + APS);
                }
                #pragma unroll
                for (int g = 0; g < 2; g++) {
                    #pragma unroll
                    for (int ml = 0; ml < 2; ml++) {
                        int mt = mp*2 + ml;
                        MMA16816(acc[mt][g*2],   ah[ml], bh[g][0], bh[g][1]);
                        MMA16816(acc[mt][g*2+1], ah[ml], bh[g][2], bh[g][3]);
                        if (AS) {
                            MMA16816(acc[mt][g*2],   al[ml], bh[g][0], bh[g][1]);
                            MMA16816(acc[mt][g*2+1], al[ml], bh[g][2], bh[g][3]);
                        }
                    }
                }
            }
        }
        if (NST == 2) {
            __syncthreads();
            if (it + 2 < NK) load_chunk(it + 2);
        }
    }

    // ---- epilogue ----
    #pragma unroll
    for (int mt = 0; mt < 4; mt++) {
        #pragma unroll
        for (int nt = 0; nt < 4; nt++) {
            #pragma unroll
            for (int half = 0; half < 2; half++) {
                int m = bm + wm*64 + mt*16 + group + half*8;
                #pragma unroll
                for (int e = 0; e < 2; e++) {
                    int n = bn + wn*32 + nt*8 + tid4*2 + e;
                    float v = acc[mt][nt][half*2 + e];
                    if (MODE == 0) {
                        float s = siluf(v + bias[n]);
                        vs_h[(size_t)m*H_ + n] = __float2half_rn(s);
                    } else if (MODE == 1) {
                        v += bias[n];
                        if (n < 512)       v = sigmf(v);
                        else if (n < 1664) v = siluf(v);
                        g_base[(size_t)m*NBASE + n] = v;
                    } else if (MODE == 2) {
                        float hx = g_base[(size_t)m*NBASE + 1664 + n];
                        float s  = siluf(v + bias[n] + hx);
                        float u  = g_base[(size_t)m*NBASE + n];
                        float xr = Xres[(size_t)m*D_ + n];
                        g_o[(size_t)m*D_ + n] = xr + u*(s - xr);
                    } else {
                        size_t row = (size_t)(cc*128 + m)*B_ + bb;
                        float rv = g_base[row*NBASE + 640 + n];
                        hr_h[row*H_ + n] = __float2half_rn(v*rv);
                    }
                }
            }
        }
    }
}

// ---------------- QK + softmax ----------------
__global__ void __launch_bounds__(256) qk_kernel(
    const float* __restrict__ qkg, const float* __restrict__ qkb,
    const float* __restrict__ rp, float* __restrict__ attn_out)
{
    extern __shared__ float sm[];
    float* qT = sm;
    float* kT = sm + 16384;
    float* sT = sm + 32768;
    float* red = sm;

    const int b = blockIdx.x >> 4;
    const int c = blockIdx.x & 15;
    const int t = threadIdx.x;
    const float qscale = 0.08838834764831845f;

    for (int idx = t; idx < 16384; idx += 256) {
        int i = idx >> 7, z = idx & 127;
        int row = (c*128 + i)*B_ + b;
        float zv = g_base[(size_t)row*NBASE + 512 + z];
        qT[z*128 + i] = (zv*qkg[z]     + qkb[z]    ) * qscale;
        kT[z*128 + i] =  zv*qkg[128+z] + qkb[128+z];
    }
    __syncthreads();

    {
        const int tx = t & 15, ty = t >> 4;
        const int i0 = ty*8, j0 = tx*8;
        float acc[8][8];
        #pragma unroll
        for (int i = 0; i < 8; i++)
            #pragma unroll
            for (int j = 0; j < 8; j++) acc[i][j] = 0.f;

        #pragma unroll 4
        for (int z = 0; z < 128; z++) {
            float qa[8], ka[8];
            *(float4*)(qa)   = *(const float4*)&qT[z*128 + i0];
            *(float4*)(qa+4) = *(const float4*)&qT[z*128 + i0 + 4];
            *(float4*)(ka)   = *(const float4*)&kT[z*128 + j0];
            *(float4*)(ka+4) = *(const float4*)&kT[z*128 + j0 + 4];
            #pragma unroll
            for (int i = 0; i < 8; i++)
                #pragma unroll
                for (int j = 0; j < 8; j++)
                    acc[i][j] = fmaf(qa[i], ka[j], acc[i][j]);
        }
        #pragma unroll
        for (int r = 0; r < 8; r++)
            #pragma unroll
            for (int cc2 = 0; cc2 < 8; cc2++) {
                int i = i0 + r, j = j0 + cc2;
                sT[j*132 + i] = acc[r][cc2] + rp[1023 + j - i];
            }
    }
    __syncthreads();

    {
        const int i = t & 127, half = t >> 7;
        const int jb = half*64;
        float mx = -1e30f;
        for (int j = jb; j < jb + 64; j++) mx = fmaxf(mx, sT[j*132 + i]);
        red[half*128 + i] = mx;
        __syncthreads();
        float M = fmaxf(red[i], red[128 + i]);
        float s = 0.f;
        for (int j = jb; j < jb + 64; j++) {
            float e = expf(sT[j*132 + i] - M);
            sT[j*132 + i] = e;
            s += e;
        }
        red[256 + half*128 + i] = s;
        __syncthreads();
        if (half == 0) red[512 + i] = 1.f / (red[256 + i] + red[384 + i]);
        __syncthreads();
    }

    size_t base = (size_t)(b*NC_ + c)*16384;
    float* aout = attn_out + base;
    for (int idx = t; idx < 16384; idx += 256) {
        int i = idx >> 7, j = idx & 127;
        float p = sT[j*132 + i] * red[512 + i];
        aout[idx] = p;
        at_h[base + idx] = __float2half_rn(p);
    }
}

// ---------------- final rmsnorm ----------------
__global__ void __launch_bounds__(256) norm_kernel(
    const float* __restrict__ ns, float* __restrict__ out)
{
    int row  = blockIdx.x*8 + (threadIdx.x >> 5);
    int lane = threadIdx.x & 31;
    const float* op = g_o + (size_t)row*512;
    float vals[16];
    float ss = 0.f;
    #pragma unroll
    for (int k = 0; k < 16; k++) {
        float v = op[lane + k*32];
        vals[k] = v;
        ss += v*v;
    }
    #pragma unroll
    for (int off = 16; off; off >>= 1) ss += __shfl_xor_sync(0xffffffffu, ss, off);
    float scale = ns[0] * rsqrtf(ss*(1.f/512.f) + 1e-6f);
    float* outp = out + (size_t)row*512;
    #pragma unroll
    for (int k = 0; k < 16; k++) outp[lane + k*32] = vals[k]*scale;
}

// ---------------- launch ----------------
extern "C" void kernel_launch(void* const* d_in, const int* in_sizes, int n_in,
                              void* d_out, int out_size)
{
    const float* x   = (const float*)d_in[0];
    const float* edl = (const float*)d_in[1];
    const float* eal = (const float*)d_in[2];
    const float* ebt = (const float*)d_in[3];
    const float* egm = (const float*)d_in[4];
    const float* eom = (const float*)d_in[5];
    const float* Wv  = (const float*)d_in[6];
    const float* bv  = (const float*)d_in[7];
    const float* Wmx = (const float*)d_in[8];
    const float* bmx = (const float*)d_in[9];
    const float* Wh  = (const float*)d_in[10];
    const float* bh  = (const float*)d_in[11];
    const float* qkg = (const float*)d_in[12];
    const float* qkb = (const float*)d_in[13];
    const float* rp  = (const float*)d_in[14];
    const float* ns  = (const float*)d_in[15];

    float* out      = (float*)d_out;
    float* attn_out = out + (size_t)L_*B_*D_;

    static cudaStream_t s2 = nullptr;
    static cudaEvent_t ev0 = nullptr, ev1 = nullptr, ev2 = nullptr;
    if (!s2) {
        cudaStreamCreateWithFlags(&s2, cudaStreamNonBlocking);
        cudaEventCreateWithFlags(&ev0, cudaEventDisableTiming);
        cudaEventCreateWithFlags(&ev1, cudaEventDisableTiming);
        cudaEventCreateWithFlags(&ev2, cudaEventDisableTiming);
        cudaFuncSetAttribute(qk_kernel, cudaFuncAttributeMaxDynamicSharedMemorySize, 198656);
        cudaFuncSetAttribute(ema_p3,    cudaFuncAttributeMaxDynamicSharedMemorySize, 16384);
        cudaFuncSetAttribute((const void*)mma_gemm<0,false,0,false>,  cudaFuncAttributeMaxDynamicSharedMemorySize, 98304);
        cudaFuncSetAttribute((const void*)mma_gemm<1,false,0,true>,   cudaFuncAttributeMaxDynamicSharedMemorySize, 98304);
        cudaFuncSetAttribute((const void*)mma_gemm<1,true,512,false>, cudaFuncAttributeMaxDynamicSharedMemorySize, 98304);
        cudaFuncSetAttribute((const void*)mma_gemm<2,false,0,false>,  cudaFuncAttributeMaxDynamicSharedMemorySize, 98304);
        cudaFuncSetAttribute((const void*)mma_gemm<3,false,0,false>,  cudaFuncAttributeMaxDynamicSharedMemorySize, 98304);
    }

    // fork: s2 does weight split concurrently with ema_p1
    cudaEventRecord(ev0, 0);
    cudaStreamWaitEvent(s2, ev0, 0);
    splitw_all<<<2112, 256, 0, s2>>>(Wv, Wmx, Wh);

    ema_p1<<<2048, 256>>>(x, edl, eal);
    cudaEventRecord(ev1, 0);

    // s2: mode-0 GEMM (needs xs_h from ema_p1 + wv_h) overlaps ema_p2/p3/mode-1
    cudaStreamWaitEvent(s2, ev1, 0);
    { dim3 g(8, 256); mma_gemm<0,false,0,false><<<g, 256, 98304, s2>>>(x, bv); }
    cudaEventRecord(ev2, s2);

    // main chain
    ema_p2<<<32, 256>>>(edl, eal);
    ema_p3<<<4096, 128, 16384>>>(x, edl, eal, ebt, egm, eom);

    { dim3 g(16, 256); mma_gemm<1,false,0,true><<<g, 256, 98304>>>(x, bmx); }   // u + r + hx
    { dim3 g(1, 256);  mma_gemm<1,true,512,false><<<g, 256, 98304>>>(x, bmx); } // z (2-pass)

    qk_kernel<<<B_*NC_, 256, 198656>>>(qkg, qkb, rp, attn_out);

    // join: mode-3 needs vs_h (mode-0 output)
    cudaStreamWaitEvent(0, ev2, 0);
    { dim3 g(8, 1, 256); mma_gemm<3,false,0,false><<<g, 256, 98304>>>(x, bv); }
    { dim3 g(4, 256);    mma_gemm<2,false,0,false><<<g, 256, 98304>>>(x, bh); }

    norm_kernel<<<MROWS/8, 256>>>(ns, out);
}

// round 17
// speedup vs baseline: 1.2071x; 1.0119x over previous
#include <cuda_runtime.h>
#include <cuda_fp16.h>
#include <stdint.h>
#include <math.h>

#define L_ 2048
#define B_ 16
#define D_ 512
#define H_ 1024
#define NC_ 16
#define NBASE 2176            // Z + H + 2D
#define MROWS (L_*B_)         // 32768
#define NCH 64                // EMA chunks
#define CHL 32                // chunk length
#define NST8 (NCH*8192)

// ---------------- fp32 scratch ----------------
__device__ float g_base[MROWS*NBASE];  // activated base: [u | z | r | hx]
__device__ float g_o   [MROWS*D_];     // pre-norm output
__device__ float e_st  [4*NST8];       // per-chunk local states
__device__ float seed_st[4*NST8];      // per-chunk seeds

// ---------------- fp16 planes ----------------
__device__ __align__(16) __half xs_h [MROWS*D_];
__device__ __align__(16) __half mxs_h[MROWS*D_],  mxs_l[MROWS*D_];
__device__ __align__(16) __half hr_h [MROWS*H_];
__device__ __align__(16) __half at_h [B_*NC_*128*128];
__device__ __align__(16) __half vs_h [MROWS*H_];
__device__ __align__(16) __half wv_h [512*1024];
__device__ __align__(16) __half wmx_h[512*2176];
__device__ __align__(16) __half wh_h [1024*512];

__device__ __forceinline__ float sigmf(float x){ return 1.0f/(1.0f + expf(-x)); }
__device__ __forceinline__ float siluf(float x){ return x/(1.0f + expf(-x)); }
__device__ __forceinline__ void split2h(float v, __half& h, __half& l){
    h = __float2half_rn(v);
    l = __float2half_rn(v - __half2float(h));
}

#define MMA16816(d, a, b0, b1) \
  asm volatile("mma.sync.aligned.m16n8k16.row.col.f32.f16.f16.f32 " \
    "{%0,%1,%2,%3}, {%4,%5,%6,%7}, {%8,%9}, {%0,%1,%2,%3};" \
    : "+f"(d[0]), "+f"(d[1]), "+f"(d[2]), "+f"(d[3]) \
    : "r"(a[0]), "r"(a[1]), "r"(a[2]), "r"(a[3]), "r"(b0), "r"(b1))

#define LDSM4(r0,r1,r2,r3,a) \
  asm volatile("ldmatrix.sync.aligned.m8n8.x4.shared.b16 {%0,%1,%2,%3}, [%4];" \
    : "=r"(r0),"=r"(r1),"=r"(r2),"=r"(r3) : "r"(a))

#define LDSM4T(r0,r1,r2,r3,a) \
  asm volatile("ldmatrix.sync.aligned.m8n8.x4.trans.shared.b16 {%0,%1,%2,%3}, [%4];" \
    : "=r"(r0),"=r"(r1),"=r"(r2),"=r"(r3) : "r"(a))

#define CPA16(s,g) asm volatile("cp.async.cg.shared.global [%0], [%1], 16;" :: "r"(s), "l"(g))

// ---------------- all 3 weights: fp32 -> fp16, one launch ----------------
__global__ void __launch_bounds__(256) splitw_all(
    const float* __restrict__ Wv, const float* __restrict__ Wmx,
    const float* __restrict__ Wh)
{
    int bx = blockIdx.x;
    const float* src; __half* dst; int off;
    if (bx < 512)       { src = Wv;  dst = wv_h;  off = bx; }
    else if (bx < 1600) { src = Wmx; dst = wmx_h; off = bx - 512; }
    else                { src = Wh;  dst = wh_h;  off = bx - 1600; }
    size_t i4 = (size_t)off*256 + threadIdx.x;
    float4 v = *(const float4*)&src[i4*4];
    size_t o = i4*4;
    dst[o+0] = __float2half_rn(v.x);
    dst[o+1] = __float2half_rn(v.y);
    dst[o+2] = __float2half_rn(v.z);
    dst[o+3] = __float2half_rn(v.w);
}

// ---------------- EMA phase 1: per-chunk local states + x->fp16 ----------------
__global__ void __launch_bounds__(256) ema_p1(
    const float* __restrict__ x, const float* __restrict__ dlt,
    const float* __restrict__ alp)
{
    int t = blockIdx.x*256 + threadIdx.x;      // 0..524287
    int c = t >> 13, bd = t & 8191;
    int d = bd & 511;
    int i0f = d*2, i1f = d*2 + 1;
    int i0b = (512 + d)*2, i1b = i0b + 1;
    float q0f = 1.f - sigmf(dlt[i0f])*sigmf(alp[i0f]);
    float q1f = 1.f - sigmf(dlt[i1f])*sigmf(alp[i1f]);
    float q0b = 1.f - sigmf(dlt[i0b])*sigmf(alp[i0b]);
    float q1b = 1.f - sigmf(dlt[i1b])*sigmf(alp[i1b]);

    float f0 = 0.f, f1 = 0.f, a0 = 0.f, a1 = 0.f, pw0 = 1.f, pw1 = 1.f;
    size_t idx = (size_t)(c*CHL)*8192 + bd;
    #pragma unroll 4
    for (int j = 0; j < CHL; j++, idx += 8192) {
        float xv = x[idx];
        f0 = fmaf(q0f, f0, xv);
        f1 = fmaf(q1f, f1, xv);
        a0 = fmaf(pw0, xv, a0);
        a1 = fmaf(pw1, xv, a1);
        pw0 *= q0b; pw1 *= q1b;
        xs_h[idx] = __float2half_rn(xv);
    }
    int o = c*8192 + bd;
    e_st[0*NST8 + o] = f0;
    e_st[1*NST8 + o] = f1;
    e_st[2*NST8 + o] = a0;
    e_st[3*NST8 + o] = a1;
}

// ---------------- EMA phase 2: hierarchical affine scan ----------------
// 256 blocks x 256 threads. Block owns 32 bd. Thread = (bd_local, role);
// role 0-3: fwd groups of 16 chunks; role 4-7: bwd groups.
__global__ void __launch_bounds__(256) ema_p2(
    const float* __restrict__ dlt, const float* __restrict__ alp)
{
    __shared__ float eg[8][32][2];
    const int bdl  = threadIdx.x & 31;
    const int role = threadIdx.x >> 5;
    const int bd = blockIdx.x*32 + bdl;
    const int d  = bd & 511;
    const bool fwd = (role < 4);
    const int g = role & 3;
    const int cbase = g*16;

    int i0 = (fwd ? d : 512 + d)*2, i1 = i0 + 1;
    float q0 = 1.f - sigmf(dlt[i0])*sigmf(alp[i0]);
    float q1 = 1.f - sigmf(dlt[i1])*sigmf(alp[i1]);
    // q^CHL (CHL=32): 5 squarings
    float q0c = q0, q1c = q1;
    #pragma unroll
    for (int i = 0; i < 5; i++) { q0c *= q0c; q1c *= q1c; }

    const int eb = fwd ? 0 : 2;
    // pass A: group-local combine (scan order)
    float E0 = 0.f, E1 = 0.f;
    if (fwd) {
        #pragma unroll
        for (int k = 0; k < 16; k++) {
            int o = (cbase + k)*8192 + bd;
            E0 = fmaf(q0c, E0, e_st[0*NST8 + o]);
            E1 = fmaf(q1c, E1, e_st[1*NST8 + o]);
        }
    } else {
        #pragma unroll
        for (int k = 15; k >= 0; k--) {
            int o = (cbase + k)*8192 + bd;
            E0 = fmaf(q0c, E0, e_st[2*NST8 + o]);
            E1 = fmaf(q1c, E1, e_st[3*NST8 + o]);
        }
    }
    eg[role][bdl][0] = E0;
    eg[role][bdl][1] = E1;
    __syncthreads();

    // Q = q^(CHL*16): 4 more squarings
    float Q0 = q0c, Q1 = q1c;
    #pragma unroll
    for (int i = 0; i < 4; i++) { Q0 *= Q0; Q1 *= Q1; }

    // cross-group prefix (<=3 steps)
    float P0 = 0.f, P1 = 0.f;
    if (fwd) {
        for (int gp = 0; gp < g; gp++) {
            P0 = fmaf(Q0, P0, eg[gp][bdl][0]);
            P1 = fmaf(Q1, P1, eg[gp][bdl][1]);
        }
    } else {
        for (int gp = 3; gp > g; gp--) {
            P0 = fmaf(Q0, P0, eg[4 + gp][bdl][0]);
            P1 = fmaf(Q1, P1, eg[4 + gp][bdl][1]);
        }
    }

    // pass B: seeds
    if (fwd) {
        #pragma unroll
        for (int k = 0; k < 16; k++) {
            int o = (cbase + k)*8192 + bd;
            seed_st[0*NST8 + o] = P0;
            seed_st[1*NST8 + o] = P1;
            P0 = fmaf(q0c, P0, e_st[0*NST8 + o]);
            P1 = fmaf(q1c, P1, e_st[1*NST8 + o]);
        }
    } else {
        #pragma unroll
        for (int k = 15; k >= 0; k--) {
            int o = (cbase + k)*8192 + bd;
            seed_st[2*NST8 + o] = P0;
            seed_st[3*NST8 + o] = P1;
            P0 = fmaf(q0c, P0, e_st[2*NST8 + o]);
            P1 = fmaf(q1c, P1, e_st[3*NST8 + o]);
        }
    }
}

// ---------------- EMA phase 3: seeded scans + silu + split ----------------
__global__ void __launch_bounds__(128) ema_p3(
    const float* __restrict__ x, const float* __restrict__ dlt,
    const float* __restrict__ alp, const float* __restrict__ bet,
    const float* __restrict__ gam, const float* __restrict__ omg)
{
    extern __shared__ float ybuf[];            // [CHL][128] = 16KB
    int t = blockIdx.x*128 + threadIdx.x;
    int tid = threadIdx.x;
    int c = t >> 13, bd = t & 8191;
    int d = bd & 511;
    const float invs = 0.7071067811865476f;

    int i0f = d*2, i1f = d*2 + 1;
    int i0b = (512 + d)*2, i1b = i0b + 1;
    float p0f = sigmf(dlt[i0f]), p1f = sigmf(dlt[i1f]);
    float p0b = sigmf(dlt[i0b]), p1b = sigmf(dlt[i1b]);
    float q0f = 1.f - p0f*sigmf(alp[i0f]);
    float q1f = 1.f - p1f*sigmf(alp[i1f]);
    float q0b = 1.f - p0b*sigmf(alp[i0b]);
    float q1b = 1.f - p1b*sigmf(alp[i1b]);
    float w0f = p0f*bet[i0f]*gam[i0f]*invs;
    float w1f = p1f*bet[i1f]*gam[i1f]*invs;
    float w0b = p0b*bet[i0b]*gam[i0b]*invs;
    float w1b = p1b*bet[i1b]*gam[i1b]*invs;
    float ow = omg[d];

    int o = c*8192 + bd;
    size_t base = (size_t)(c*CHL)*8192 + bd;

    {
        float g0 = seed_st[2*NST8 + o];
        float g1 = seed_st[3*NST8 + o];
        size_t idx = base + (size_t)(CHL-1)*8192;
        #pragma unroll 4
        for (int j = CHL-1; j >= 0; j--, idx -= 8192) {
            float xv = x[idx];
            g0 = fmaf(q0b, g0, xv);
            g1 = fmaf(q1b, g1, xv);
            ybuf[j*128 + tid] = fmaf(w0b, g0, w1b*g1);
        }
    }
    {
        float f0 = seed_st[0*NST8 + o];
        float f1 = seed_st[1*NST8 + o];
        size_t idx = base;
        #pragma unroll 4
        for (int j = 0; j < CHL; j++, idx += 8192) {
            float xv = x[idx];
            f0 = fmaf(q0f, f0, xv);
            f1 = fmaf(q1f, f1, xv);
            float y = ybuf[j*128 + tid] + fmaf(w0f, f0, fmaf(w1f, f1, xv*ow));
            split2h(siluf(y), mxs_h[idx], mxs_l[idx]);
        }
    }
}

// ---------------- pipelined fp16 tensor-core GEMM (K-chunk 64) ----------------
// MODE 0: vs_h  = fp16(silu(xs @ Wv + bv))         N=1024 K=512
// MODE 1: g_base= act(mxs @ Wmx + bmx)             (u/r/hx merged 1-pass, z 2-pass)
// MODE 2: g_o   = gate(silu(hr @ Wh + bh + hx))    N=512  K=1024
// MODE 3: hr_h  = fp16((attn @ v) * r)  (256 bat)  N=1024 K=128
template<int MODE, bool AS, int NOFF, bool M1MAP>
__global__ void __launch_bounds__(256, 2) mma_gemm(
    const float* __restrict__ Xres, const float* __restrict__ bias)
{
    constexpr int K   = (MODE==2) ? 1024 : (MODE==3) ? 128 : 512;
    constexpr int ldA = (MODE==2) ? 1024 : (MODE==3) ? 128 : 512;
    constexpr int ldB = (MODE==0) ? 1024 : (MODE==1) ? 2176 : (MODE==2) ? 512 : 16384;
    constexpr int NK  = K/64;
    constexpr int APS = 128*128;
    constexpr int BOFF = (AS ? 2 : 1)*APS;
    constexpr int STAGE = BOFF + 16384;
    constexpr int NST = AS ? 2 : 3;
    constexpr int NAE = AS ? 8 : 4;

    extern __shared__ __align__(128) char smem_raw[];
    const uint32_t sb = (uint32_t)__cvta_generic_to_shared(smem_raw);

    const int t = threadIdx.x;
    const int warp = t >> 5, lane = t & 31;
    const int wm = warp & 1, wn = warp >> 1;
    const int group = lane >> 2, tid4 = lane & 3;
    const int mat = lane >> 3, rim = lane & 7;
    const int rOff = ((mat & 1) << 3) + rim;
    const int cOff = mat >> 1;

    int bn;
    if (M1MAP) bn = (blockIdx.x < 4) ? blockIdx.x*128 : 640 + (blockIdx.x - 4)*128;
    else       bn = NOFF + blockIdx.x * 128;
    const int bm = (MODE==3) ? 0 : blockIdx.y * 128;

    int bb = 0, cc = 0, batch = 0;
    if (MODE == 3) { batch = blockIdx.z; bb = batch >> 4; cc = batch & 15; }

    const __half *pA0, *pA1 = nullptr, *pB0;
    if (MODE == 0) { pA0 = xs_h  + (size_t)bm*ldA;
                     pB0 = wv_h  + bn; }
    else if (MODE == 1) { pA0 = mxs_h + (size_t)bm*ldA; pA1 = mxs_l + (size_t)bm*ldA;
                          pB0 = wmx_h + bn; }
    else if (MODE == 2) { pA0 = hr_h  + (size_t)bm*ldA;
                          pB0 = wh_h  + bn; }
    else { pA0 = at_h + (size_t)batch*16384;
           pB0 = vs_h + (size_t)(cc*2048 + bb)*H_ + bn; }

    const __half* gA[NAE]; uint32_t sA[NAE];
    #pragma unroll
    for (int e = 0; e < NAE; e++) {
        int idx = e*256 + t;
        int plane = idx >> 10, w = idx & 1023;
        int r = w >> 3, c = w & 7;
        gA[e] = (plane ? pA1 : pA0) + (size_t)r*ldA + c*8;
        sA[e] = sb + plane*APS + r*128 + (((uint32_t)(c ^ (r & 7))) << 4);
    }
    const __half* gB[4]; uint32_t sB[4];
    #pragma unroll
    for (int e = 0; e < 4; e++) {
        int idx = e*256 + t;
        int r = idx >> 4, c = idx & 15;
        gB[e] = pB0 + (size_t)r*ldB + c*8;
        sB[e] = sb + BOFF + r*256 + (((uint32_t)(c ^ (r & 7))) << 4);
    }

    auto load_chunk = [&](int ck) {
        uint32_t so = (uint32_t)(ck % NST) * STAGE;
        int ka = ck * 64;
        #pragma unroll
        for (int e = 0; e < NAE; e++) CPA16(sA[e] + so, gA[e] + ka);
        #pragma unroll
        for (int e = 0; e < 4; e++) CPA16(sB[e] + so, gB[e] + (size_t)ka*ldB);
        asm volatile("cp.async.commit_group;");
    };

    float acc[4][4][4];
    #pragma unroll
    for (int a = 0; a < 4; a++)
        #pragma unroll
        for (int b2 = 0; b2 < 4; b2++)
            #pragma unroll
            for (int e = 0; e < 4; e++) acc[a][b2][e] = 0.f;

    load_chunk(0);
    load_chunk(1);

    for (int it = 0; it < NK; it++) {
        if (it + 1 < NK) asm volatile("cp.async.wait_group 1;" ::: "memory");
        else             asm volatile("cp.async.wait_group 0;" ::: "memory");
        __syncthreads();
        if (NST == 3 && it + 2 < NK) load_chunk(it + 2);

        const uint32_t stg = sb + (uint32_t)(it % NST)*STAGE;
        #pragma unroll
        for (int ks = 0; ks < 4; ks++) {
            uint32_t bh[2][4];
            const int kin = ks*16 + rOff;
            #pragma unroll
            for (int g = 0; g < 2; g++) {
                int cB = wn*4 + g*2 + cOff;
                uint32_t bd = stg + BOFF + kin*256 + (((uint32_t)(cB ^ (kin & 7))) << 4);
                LDSM4T(bh[g][0], bh[g][1], bh[g][2], bh[g][3], bd);
            }
            #pragma unroll
            for (int mp = 0; mp < 2; mp++) {
                uint32_t ah[2][4], al[2][4];
                #pragma unroll
                for (int ml = 0; ml < 2; ml++) {
                    int row = wm*64 + (mp*2 + ml)*16 + rOff;
                    int cA = ks*2 + cOff;
                    uint32_t ad = stg + row*128 + (((uint32_t)(cA ^ (row & 7))) << 4);
                    LDSM4(ah[ml][0], ah[ml][1], ah[ml][2], ah[ml][3], ad);
                    if (AS) LDSM4(al[ml][0], al[ml][1], al[ml][2], al[ml][3], ad + APS);
                }
                #pragma unroll
                for (int g = 0; g < 2; g++) {
                    #pragma unroll
                    for (int ml = 0; ml < 2; ml++) {
                        int mt = mp*2 + ml;
                        MMA16816(acc[mt][g*2],   ah[ml], bh[g][0], bh[g][1]);
                        MMA16816(acc[mt][g*2+1], ah[ml], bh[g][2], bh[g][3]);
                        if (AS) {
                            MMA16816(acc[mt][g*2],   al[ml], bh[g][0], bh[g][1]);
                            MMA16816(acc[mt][g*2+1], al[ml], bh[g][2], bh[g][3]);
                        }
                    }
                }
            }
        }
        if (NST == 2) {
            __syncthreads();
            if (it + 2 < NK) load_chunk(it + 2);
        }
    }

    // ---- epilogue ----
    #pragma unroll
    for (int mt = 0; mt < 4; mt++) {
        #pragma unroll
        for (int nt = 0; nt < 4; nt++) {
            #pragma unroll
            for (int half = 0; half < 2; half++) {
                int m = bm + wm*64 + mt*16 + group + half*8;
                #pragma unroll
                for (int e = 0; e < 2; e++) {
                    int n = bn + wn*32 + nt*8 + tid4*2 + e;
                    float v = acc[mt][nt][half*2 + e];
                    if (MODE == 0) {
                        float s = siluf(v + bias[n]);
                        vs_h[(size_t)m*H_ + n] = __float2half_rn(s);
                    } else if (MODE == 1) {
                        v += bias[n];
                        if (n < 512)       v = sigmf(v);
                        else if (n < 1664) v = siluf(v);
                        g_base[(size_t)m*NBASE + n] = v;
                    } else if (MODE == 2) {
                        float hx = g_base[(size_t)m*NBASE + 1664 + n];
                        float s  = siluf(v + bias[n] + hx);
                        float u  = g_base[(size_t)m*NBASE + n];
                        float xr = Xres[(size_t)m*D_ + n];
                        g_o[(size_t)m*D_ + n] = xr + u*(s - xr);
                    } else {
                        size_t row = (size_t)(cc*128 + m)*B_ + bb;
                        float rv = g_base[row*NBASE + 640 + n];
                        hr_h[row*H_ + n] = __float2half_rn(v*rv);
                    }
                }
            }
        }
    }
}

// ---------------- QK + softmax ----------------
__global__ void __launch_bounds__(256) qk_kernel(
    const float* __restrict__ qkg, const float* __restrict__ qkb,
    const float* __restrict__ rp, float* __restrict__ attn_out)
{
    extern __shared__ float sm[];
    float* qT = sm;
    float* kT = sm + 16384;
    float* sT = sm + 32768;
    float* red = sm;

    const int b = blockIdx.x >> 4;
    const int c = blockIdx.x & 15;
    const int t = threadIdx.x;
    const float qscale = 0.08838834764831845f;

    for (int idx = t; idx < 16384; idx += 256) {
        int i = idx >> 7, z = idx & 127;
        int row = (c*128 + i)*B_ + b;
        float zv = g_base[(size_t)row*NBASE + 512 + z];
        qT[z*128 + i] = (zv*qkg[z]     + qkb[z]    ) * qscale;
        kT[z*128 + i] =  zv*qkg[128+z] + qkb[128+z];
    }
    __syncthreads();

    {
        const int tx = t & 15, ty = t >> 4;
        const int i0 = ty*8, j0 = tx*8;
        float acc[8][8];
        #pragma unroll
        for (int i = 0; i < 8; i++)
            #pragma unroll
            for (int j = 0; j < 8; j++) acc[i][j] = 0.f;

        #pragma unroll 4
        for (int z = 0; z < 128; z++) {
            float qa[8], ka[8];
            *(float4*)(qa)   = *(const float4*)&qT[z*128 + i0];
            *(float4*)(qa+4) = *(const float4*)&qT[z*128 + i0 + 4];
            *(float4*)(ka)   = *(const float4*)&kT[z*128 + j0];
            *(float4*)(ka+4) = *(const float4*)&kT[z*128 + j0 + 4];
            #pragma unroll
            for (int i = 0; i < 8; i++)
                #pragma unroll
                for (int j = 0; j < 8; j++)
                    acc[i][j] = fmaf(qa[i], ka[j], acc[i][j]);
        }
        #pragma unroll
        for (int r = 0; r < 8; r++)
            #pragma unroll
            for (int cc2 = 0; cc2 < 8; cc2++) {
                int i = i0 + r, j = j0 + cc2;
                sT[j*132 + i] = acc[r][cc2] + rp[1023 + j - i];
            }
    }
    __syncthreads();

    {
        const int i = t & 127, half = t >> 7;
        const int jb = half*64;
        float mx = -1e30f;
        for (int j = jb; j < jb + 64; j++) mx = fmaxf(mx, sT[j*132 + i]);
        red[half*128 + i] = mx;
        __syncthreads();
        float M = fmaxf(red[i], red[128 + i]);
        float s = 0.f;
        for (int j = jb; j < jb + 64; j++) {
            float e = expf(sT[j*132 + i] - M);
            sT[j*132 + i] = e;
            s += e;
        }
        red[256 + half*128 + i] = s;
        __syncthreads();
        if (half == 0) red[512 + i] = 1.f / (red[256 + i] + red[384 + i]);
        __syncthreads();
    }

    size_t base = (size_t)(b*NC_ + c)*16384;
    float* aout = attn_out + base;
    for (int idx = t; idx < 16384; idx += 256) {
        int i = idx >> 7, j = idx & 127;
        float p = sT[j*132 + i] * red[512 + i];
        aout[idx] = p;
        at_h[base + idx] = __float2half_rn(p);
    }
}

// ---------------- final rmsnorm ----------------
__global__ void __launch_bounds__(256) norm_kernel(
    const float* __restrict__ ns, float* __restrict__ out)
{
    int row  = blockIdx.x*8 + (threadIdx.x >> 5);
    int lane = threadIdx.x & 31;
    const float* op = g_o + (size_t)row*512;
    float vals[16];
    float ss = 0.f;
    #pragma unroll
    for (int k = 0; k < 16; k++) {
        float v = op[lane + k*32];
        vals[k] = v;
        ss += v*v;
    }
    #pragma unroll
    for (int off = 16; off; off >>= 1) ss += __shfl_xor_sync(0xffffffffu, ss, off);
    float scale = ns[0] * rsqrtf(ss*(1.f/512.f) + 1e-6f);
    float* outp = out + (size_t)row*512;
    #pragma unroll
    for (int k = 0; k < 16; k++) outp[lane + k*32] = vals[k]*scale;
}

// ---------------- launch ----------------
extern "C" void kernel_launch(void* const* d_in, const int* in_sizes, int n_in,
                              void* d_out, int out_size)
{
    const float* x   = (const float*)d_in[0];
    const float* edl = (const float*)d_in[1];
    const float* eal = (const float*)d_in[2];
    const float* ebt = (const float*)d_in[3];
    const float* egm = (const float*)d_in[4];
    const float* eom = (const float*)d_in[5];
    const float* Wv  = (const float*)d_in[6];
    const float* bv  = (const float*)d_in[7];
    const float* Wmx = (const float*)d_in[8];
    const float* bmx = (const float*)d_in[9];
    const float* Wh  = (const float*)d_in[10];
    const float* bh  = (const float*)d_in[11];
    const float* qkg = (const float*)d_in[12];
    const float* qkb = (const float*)d_in[13];
    const float* rp  = (const float*)d_in[14];
    const float* ns  = (const float*)d_in[15];

    float* out      = (float*)d_out;
    float* attn_out = out + (size_t)L_*B_*D_;

    static cudaStream_t s2 = nullptr;
    static cudaEvent_t ev0 = nullptr, ev1 = nullptr, ev2 = nullptr;
    if (!s2) {
        cudaStreamCreateWithFlags(&s2, cudaStreamNonBlocking);
        cudaEventCreateWithFlags(&ev0, cudaEventDisableTiming);
        cudaEventCreateWithFlags(&ev1, cudaEventDisableTiming);
        cudaEventCreateWithFlags(&ev2, cudaEventDisableTiming);
        cudaFuncSetAttribute(qk_kernel, cudaFuncAttributeMaxDynamicSharedMemorySize, 198656);
        cudaFuncSetAttribute(ema_p3,    cudaFuncAttributeMaxDynamicSharedMemorySize, 16384);
        cudaFuncSetAttribute((const void*)mma_gemm<0,false,0,false>,  cudaFuncAttributeMaxDynamicSharedMemorySize, 98304);
        cudaFuncSetAttribute((const void*)mma_gemm<1,false,0,true>,   cudaFuncAttributeMaxDynamicSharedMemorySize, 98304);
        cudaFuncSetAttribute((const void*)mma_gemm<1,true,512,false>, cudaFuncAttributeMaxDynamicSharedMemorySize, 98304);
        cudaFuncSetAttribute((const void*)mma_gemm<2,false,0,false>,  cudaFuncAttributeMaxDynamicSharedMemorySize, 98304);
        cudaFuncSetAttribute((const void*)mma_gemm<3,false,0,false>,  cudaFuncAttributeMaxDynamicSharedMemorySize, 98304);
    }

    // fork: s2 does weight split concurrently with ema_p1
    cudaEventRecord(ev0, 0);
    cudaStreamWaitEvent(s2, ev0, 0);
    splitw_all<<<2112, 256, 0, s2>>>(Wv, Wmx, Wh);

    ema_p1<<<2048, 256>>>(x, edl, eal);
    cudaEventRecord(ev1, 0);

    // s2: mode-0 GEMM (needs xs_h from ema_p1 + wv_h) overlaps ema_p2/p3/mode-1
    cudaStreamWaitEvent(s2, ev1, 0);
    { dim3 g(8, 256); mma_gemm<0,false,0,false><<<g, 256, 98304, s2>>>(x, bv); }
    cudaEventRecord(ev2, s2);

    // main chain
    ema_p2<<<256, 256>>>(edl, eal);
    ema_p3<<<4096, 128, 16384>>>(x, edl, eal, ebt, egm, eom);

    { dim3 g(16, 256); mma_gemm<1,false,0,true><<<g, 256, 98304>>>(x, bmx); }   // u + r + hx
    { dim3 g(1, 256);  mma_gemm<1,true,512,false><<<g, 256, 98304>>>(x, bmx); } // z (2-pass)

    qk_kernel<<<B_*NC_, 256, 198656>>>(qkg, qkb, rp, attn_out);

    // join: mode-3 needs vs_h (mode-0 output)
    cudaStreamWaitEvent(0, ev2, 0);
    { dim3 g(8, 1, 256); mma_gemm<3,false,0,false><<<g, 256, 98304>>>(x, bv); }
    { dim3 g(4, 256);    mma_gemm<2,false,0,false><<<g, 256, 98304>>>(x, bh); }

    norm_kernel<<<MROWS/8, 256>>>(ns, out);
}